// round 6
// baseline (speedup 1.0000x reference)
#include <cuda_runtime.h>
#include <cuda_bf16.h>
#include <math.h>
#include <stdint.h>

// ===========================================================================
// Static scratch (B=4096, N=8192, D<=1024 fixed by dataset)
// ===========================================================================
__device__ float g_sum[1024];
__device__ float g_sumsq[1024];
__device__ float g_a[1024];
__device__ float g_dd[1024];
__device__ float g_bias2[1024];
__device__ float g_k2[8192];
__device__ __nv_bfloat16 g_P1h[8192 * 1024], g_P1l[8192 * 1024];
__device__ __nv_bfloat16 g_P2h[8192 * 1024], g_P2l[8192 * 1024];
__device__ __nv_bfloat16 g_WTh[1024 * 1024], g_WTl[1024 * 1024];
__device__ __nv_bfloat16 g_qh[4096 * 256], g_ql[4096 * 256];
__device__ __nv_bfloat16 g_kh[8192 * 256], g_kl[8192 * 256];
__device__ float g_pm[4096 * 64], g_pl[4096 * 64], g_pw[4096 * 64];

// ===========================================================================
// Prep kernels
// ===========================================================================
__global__ void zero_two(float* a, float* b, int n) {
    int i = blockIdx.x * blockDim.x + threadIdx.x;
    if (i < n) { a[i] = 0.f; b[i] = 0.f; }
}
__global__ void zero_one(float* a, int n) {
    int i = blockIdx.x * blockDim.x + threadIdx.x;
    if (i < n) a[i] = 0.f;
}

// fp32 -> bf16 hi/lo split + column stats accumulation (layer-1 input)
__global__ void split_stats(const float* __restrict__ X,
                            __nv_bfloat16* __restrict__ hi,
                            __nv_bfloat16* __restrict__ lo,
                            int R, int Din) {
    int c = blockIdx.x * blockDim.x + threadIdx.x;
    if (c >= Din) return;
    int chunk = R / gridDim.y;
    int r0 = blockIdx.y * chunk;
    float s = 0.f, s2 = 0.f;
    for (int r = r0; r < r0 + chunk; ++r) {
        size_t i = (size_t)r * Din + c;
        float v = X[i];
        __nv_bfloat16 h = __float2bfloat16(v);
        hi[i] = h;
        lo[i] = __float2bfloat16(v - __bfloat162float(h));
        s += v;
        s2 = fmaf(v, v, s2);
    }
    atomicAdd(&g_sum[c], s);
    atomicAdd(&g_sumsq[c], s2);
}

// finalize BN stats (Din) + init bias2 (Dout) + zero stats for next layer
__global__ void finalize_bias(int R, int Din, int Dout,
                              const float* __restrict__ gam,
                              const float* __restrict__ bet,
                              const float* __restrict__ b) {
    int c = blockIdx.x * blockDim.x + threadIdx.x;
    if (c < Din) {
        float inv = 1.0f / (float)R;
        float mean = g_sum[c] * inv;
        float var = g_sumsq[c] * inv - mean * mean;
        float a = gam[c] * rsqrtf(var + 1e-5f);
        g_a[c] = a;
        g_dd[c] = bet[c] - mean * a;
    }
    if (c < Dout) {
        g_bias2[c] = b[c];
        g_sum[c] = 0.f;
        g_sumsq[c] = 0.f;
    }
}

// WT[n,k] = a[k]*W[k,n] split to bf16 hi/lo (transpose) + bias2 accumulation
__global__ void wprep_bias(const float* __restrict__ W, int Din, int Dout,
                           __nv_bfloat16* __restrict__ WTh,
                           __nv_bfloat16* __restrict__ WTl) {
    __shared__ float tile[32][33];
    __shared__ float sbias[8][32];
    int k0 = blockIdx.y * 32, n0 = blockIdx.x * 32;
    int tx = threadIdx.x, ty = threadIdx.y;
    float bp = 0.f;
    for (int i = ty; i < 32; i += 8) {
        float w = W[(size_t)(k0 + i) * Dout + n0 + tx];
        tile[i][tx] = g_a[k0 + i] * w;
        bp = fmaf(g_dd[k0 + i], w, bp);
    }
    sbias[ty][tx] = bp;
    __syncthreads();
    if (ty == 0) {
        float s = 0.f;
#pragma unroll
        for (int j = 0; j < 8; ++j) s += sbias[j][tx];
        atomicAdd(&g_bias2[n0 + tx], s);
    }
    for (int i = ty; i < 32; i += 8) {
        float v = tile[tx][i];
        size_t idx = (size_t)(n0 + i) * Din + (k0 + tx);
        __nv_bfloat16 h = __float2bfloat16(v);
        WTh[idx] = h;
        WTl[idx] = __float2bfloat16(v - __bfloat162float(h));
    }
}

// ===========================================================================
// GEMM machinery: CTA 128x128, K-tile 32, 2-stage cp.async, 4 warps (2x2),
// warp tile 64x64, ldmatrix, 3-product bf16 emulation, 128 thr, 2 CTA/SM.
// ===========================================================================
#define LDKB 80                 // smem bytes per row (32 bf16 + 16B pad)
#define TILE_B (128 * LDKB)     // 10240 B
#define STAGE_B (4 * TILE_B)    // 40960 B (Ah,Al,Bh,Bl)
#define GEMM_SMEM (2 * STAGE_B) // 81920 B

__device__ __forceinline__ void mma_bf16(float* d, const uint32_t* a, const uint32_t* b) {
    asm volatile("mma.sync.aligned.m16n8k16.row.col.f32.bf16.bf16.f32 "
        "{%0,%1,%2,%3}, {%4,%5,%6,%7}, {%8,%9}, {%0,%1,%2,%3};"
        : "+f"(d[0]), "+f"(d[1]), "+f"(d[2]), "+f"(d[3])
        : "r"(a[0]), "r"(a[1]), "r"(a[2]), "r"(a[3]), "r"(b[0]), "r"(b[1]));
}
__device__ __forceinline__ void ldsm4(uint32_t* r, uint32_t addr) {
    asm volatile("ldmatrix.sync.aligned.m8n8.x4.shared.b16 {%0,%1,%2,%3}, [%4];"
        : "=r"(r[0]), "=r"(r[1]), "=r"(r[2]), "=r"(r[3]) : "r"(addr));
}

// Fill smem stage s with K-tile t. 2048 16B chunks, 128 threads -> 16 each.
#define FILL_TILE(t, s)                                                        \
    do {                                                                       \
        char* base_ = smem + (s) * STAGE_B;                                    \
        const int k0_ = (t) << 5;                                              \
        _Pragma("unroll")                                                      \
        for (int l_ = 0; l_ < 16; ++l_) {                                      \
            int id_ = tid + (l_ << 7);                                         \
            int which_ = id_ >> 9;                                             \
            int e_ = id_ & 511;                                                \
            int row_ = e_ >> 2, c4_ = e_ & 3;                                  \
            const __nv_bfloat16* src_ =                                        \
                (which_ == 0) ? Ah : (which_ == 1) ? Al : (which_ == 2) ? Bh : Bl; \
            int grow_ = ((which_ < 2) ? m0 : n0) + row_;                       \
            const char* gp_ = (const char*)(src_ + (size_t)grow_ * K + k0_) + (c4_ << 4); \
            uint32_t sp_ = (uint32_t)__cvta_generic_to_shared(                 \
                base_ + which_ * TILE_B + row_ * LDKB + (c4_ << 4));           \
            asm volatile("cp.async.cg.shared.global [%0], [%1], 16;" :: "r"(sp_), "l"(gp_)); \
        }                                                                      \
        asm volatile("cp.async.commit_group;");                                \
    } while (0)

#define MMA_MAINLOOP()                                                         \
    do {                                                                       \
        FILL_TILE(0, 0);                                                       \
        for (int t = 0; t < T; ++t) {                                          \
            if (t + 1 < T) {                                                   \
                FILL_TILE(t + 1, (t + 1) & 1);                                 \
                asm volatile("cp.async.wait_group 1;");                        \
            } else {                                                           \
                asm volatile("cp.async.wait_group 0;");                        \
            }                                                                  \
            __syncthreads();                                                   \
            const uint32_t st_ = (uint32_t)((t & 1) * STAGE_B);                \
            _Pragma("unroll")                                                  \
            for (int kk = 0; kk < 2; ++kk) {                                   \
                const uint32_t kb_ = st_ + (kk << 5);                          \
                uint32_t bh_[8][2], bl_[8][2], tmp_[4];                        \
                _Pragma("unroll")                                              \
                for (int p = 0; p < 4; ++p) {                                  \
                    ldsm4(tmp_, bBase[p] + kb_);                               \
                    bh_[2 * p][0] = tmp_[0]; bh_[2 * p][1] = tmp_[2];          \
                    bh_[2 * p + 1][0] = tmp_[1]; bh_[2 * p + 1][1] = tmp_[3];  \
                    ldsm4(tmp_, bBase[p] + kb_ + TILE_B);                      \
                    bl_[2 * p][0] = tmp_[0]; bl_[2 * p][1] = tmp_[2];          \
                    bl_[2 * p + 1][0] = tmp_[1]; bl_[2 * p + 1][1] = tmp_[3];  \
                }                                                              \
                _Pragma("unroll")                                              \
                for (int mt = 0; mt < 4; ++mt) {                               \
                    uint32_t ah_[4], al_[4];                                   \
                    ldsm4(ah_, aBase[mt] + kb_);                               \
                    ldsm4(al_, aBase[mt] + kb_ + TILE_B);                      \
                    _Pragma("unroll")                                          \
                    for (int nt = 0; nt < 8; ++nt) {                           \
                        mma_bf16(acc[mt][nt], ah_, bh_[nt]);                   \
                        mma_bf16(acc[mt][nt], ah_, bl_[nt]);                   \
                        mma_bf16(acc[mt][nt], al_, bh_[nt]);                   \
                    }                                                          \
                }                                                              \
            }                                                                  \
            __syncthreads();                                                   \
        }                                                                      \
    } while (0)

#define GEMM_PREAMBLE()                                                        \
    const int tid = threadIdx.x;                                               \
    const int wid = tid >> 5, lane = tid & 31;                                 \
    const int g = lane >> 2;                                                   \
    const int cc = (lane & 3) * 2;                                             \
    const int wm = wid >> 1, wn = wid & 1;                                     \
    const int m0 = blockIdx.y * 128, n0 = blockIdx.x * 128;                    \
    const int T = K >> 5;                                                      \
    uint32_t sbase = (uint32_t)__cvta_generic_to_shared(smem);                 \
    const int lrow = lane & 15, lcol = (lane >> 4) << 4;                       \
    uint32_t aBase[4], bBase[4];                                               \
    _Pragma("unroll")                                                          \
    for (int mt = 0; mt < 4; ++mt)                                             \
        aBase[mt] = sbase + (wm * 64 + mt * 16 + lrow) * LDKB + lcol;          \
    _Pragma("unroll")                                                          \
    for (int p = 0; p < 4; ++p)                                                \
        bBase[p] = sbase + 2 * TILE_B + (wn * 64 + p * 16 + lrow) * LDKB + lcol; \
    float acc[4][8][4];                                                        \
    _Pragma("unroll")                                                          \
    for (int i = 0; i < 4; ++i)                                                \
        _Pragma("unroll")                                                      \
        for (int j = 0; j < 8; ++j)                                            \
            _Pragma("unroll")                                                  \
            for (int r = 0; r < 4; ++r) acc[i][j][r] = 0.f;

// ===========================================================================
// Trunk GEMM: Y = tanh((Ah+Al)@(Bh+Bl)^T + bias2) -> bf16 hi/lo
// accum 1: + column stats of tanh into g_sum/g_sumsq
// accum 2: + row sumsq of tanh into g_k2
// ===========================================================================
__global__ __launch_bounds__(128, 2) void gemm_trunk(
    const __nv_bfloat16* __restrict__ Ah, const __nv_bfloat16* __restrict__ Al,
    const __nv_bfloat16* __restrict__ Bh, const __nv_bfloat16* __restrict__ Bl,
    int K, int ldOut, int accum,
    __nv_bfloat16* __restrict__ Yh, __nv_bfloat16* __restrict__ Yl)
{
    extern __shared__ __align__(16) char smem[];
    GEMM_PREAMBLE();
    MMA_MAINLOOP();

    float* s_sum = (float*)smem;
    float* s_sq  = (float*)smem + 128;
    if (accum) {
        if (tid < 128) { s_sum[tid] = 0.f; s_sq[tid] = 0.f; }
        __syncthreads();
    }

#pragma unroll
    for (int mt = 0; mt < 4; ++mt) {
#pragma unroll
        for (int nt = 0; nt < 8; ++nt) {
            int row = m0 + wm * 64 + mt * 16 + g;
            int col = n0 + wn * 64 + nt * 8 + cc;
            float* a = acc[mt][nt];
            float bA = g_bias2[col], bB = g_bias2[col + 1];
#pragma unroll
            for (int h = 0; h < 2; ++h) {
                int r = row + h * 8;
                float v0 = tanhf(a[h * 2 + 0] + bA);
                float v1 = tanhf(a[h * 2 + 1] + bB);
                a[h * 2 + 0] = v0;
                a[h * 2 + 1] = v1;
                __nv_bfloat162 hp, lp;
                hp.x = __float2bfloat16(v0);
                hp.y = __float2bfloat16(v1);
                lp.x = __float2bfloat16(v0 - __bfloat162float(hp.x));
                lp.y = __float2bfloat16(v1 - __bfloat162float(hp.y));
                *(uint32_t*)(Yh + (size_t)r * ldOut + col) = *(uint32_t*)&hp;
                *(uint32_t*)(Yl + (size_t)r * ldOut + col) = *(uint32_t*)&lp;
            }
        }
    }

    if (accum == 1) {
#pragma unroll
        for (int nt = 0; nt < 8; ++nt) {
            int lc = wn * 64 + nt * 8 + cc;
            float s0 = 0.f, q0 = 0.f, s1 = 0.f, q1 = 0.f;
#pragma unroll
            for (int mt = 0; mt < 4; ++mt) {
                float* a = acc[mt][nt];
#pragma unroll
                for (int h = 0; h < 2; ++h) {
                    s0 += a[h * 2 + 0]; q0 = fmaf(a[h * 2 + 0], a[h * 2 + 0], q0);
                    s1 += a[h * 2 + 1]; q1 = fmaf(a[h * 2 + 1], a[h * 2 + 1], q1);
                }
            }
            atomicAdd(&s_sum[lc], s0);     atomicAdd(&s_sq[lc], q0);
            atomicAdd(&s_sum[lc + 1], s1); atomicAdd(&s_sq[lc + 1], q1);
        }
        __syncthreads();
        if (tid < 128) {
            atomicAdd(&g_sum[n0 + tid], s_sum[tid]);
            atomicAdd(&g_sumsq[n0 + tid], s_sq[tid]);
        }
    } else if (accum == 2) {
#pragma unroll
        for (int mt = 0; mt < 4; ++mt) {
#pragma unroll
            for (int h = 0; h < 2; ++h) {
                int lr = wm * 64 + mt * 16 + h * 8 + g;
                float s = 0.f;
#pragma unroll
                for (int nt = 0; nt < 8; ++nt) {
                    float v0 = acc[mt][nt][h * 2 + 0];
                    float v1 = acc[mt][nt][h * 2 + 1];
                    s = fmaf(v0, v0, s);
                    s = fmaf(v1, v1, s);
                }
                atomicAdd(&s_sum[lr], s);
            }
        }
        __syncthreads();
        if (tid < 128) atomicAdd(&g_k2[m0 + tid], s_sum[tid]);
    }
}

// ===========================================================================
// Flash sim+softmax: 128x128 logits (2*q.k - k2), partial softmax with
// y-weighting -> (max, expsum, wsum) per row per key-split.
// ===========================================================================
__global__ __launch_bounds__(128, 2) void sim_flash(
    const __nv_bfloat16* __restrict__ Ah, const __nv_bfloat16* __restrict__ Al,
    const __nv_bfloat16* __restrict__ Bh, const __nv_bfloat16* __restrict__ Bl,
    const float* __restrict__ y, int K, int nsplit)
{
    extern __shared__ __align__(16) char smem[];
    GEMM_PREAMBLE();
    MMA_MAINLOOP();

    float* red = (float*)smem;   // [128 rows][2 wn][3]
#pragma unroll
    for (int mt = 0; mt < 4; ++mt) {
#pragma unroll
        for (int h = 0; h < 2; ++h) {
            float lg[8][2];
            float mx = -3.4e38f;
#pragma unroll
            for (int nt = 0; nt < 8; ++nt) {
                int col = n0 + wn * 64 + nt * 8 + cc;
#pragma unroll
                for (int c2 = 0; c2 < 2; ++c2) {
                    float v = 2.f * acc[mt][nt][h * 2 + c2] - g_k2[col + c2];
                    lg[nt][c2] = v;
                    mx = fmaxf(mx, v);
                }
            }
            mx = fmaxf(mx, __shfl_xor_sync(0xFFFFFFFF, mx, 1));
            mx = fmaxf(mx, __shfl_xor_sync(0xFFFFFFFF, mx, 2));
            float s = 0.f, w = 0.f;
#pragma unroll
            for (int nt = 0; nt < 8; ++nt) {
                int col = n0 + wn * 64 + nt * 8 + cc;
#pragma unroll
                for (int c2 = 0; c2 < 2; ++c2) {
                    float e = __expf(lg[nt][c2] - mx);
                    s += e;
                    w = fmaf(e, y[col + c2], w);
                }
            }
            s += __shfl_xor_sync(0xFFFFFFFF, s, 1);
            s += __shfl_xor_sync(0xFFFFFFFF, s, 2);
            w += __shfl_xor_sync(0xFFFFFFFF, w, 1);
            w += __shfl_xor_sync(0xFFFFFFFF, w, 2);
            if ((lane & 3) == 0) {
                int lr = wm * 64 + mt * 16 + h * 8 + g;
                red[(lr * 2 + wn) * 3 + 0] = mx;
                red[(lr * 2 + wn) * 3 + 1] = s;
                red[(lr * 2 + wn) * 3 + 2] = w;
            }
        }
    }
    __syncthreads();
    if (tid < 128) {
        float m0v = red[(tid * 2 + 0) * 3 + 0];
        float m1v = red[(tid * 2 + 1) * 3 + 0];
        float M = fmaxf(m0v, m1v);
        float e0 = __expf(m0v - M), e1 = __expf(m1v - M);
        float L = red[(tid * 2 + 0) * 3 + 1] * e0 + red[(tid * 2 + 1) * 3 + 1] * e1;
        float W = red[(tid * 2 + 0) * 3 + 2] * e0 + red[(tid * 2 + 1) * 3 + 2] * e1;
        size_t idx = (size_t)(m0 + tid) * nsplit + blockIdx.x;
        g_pm[idx] = M;
        g_pl[idx] = L;
        g_pw[idx] = W;
    }
}

// ===========================================================================
// Combine partials: out[row] = clip( W/L ) with log-sum-exp merge of 64 splits
// ===========================================================================
__global__ void combine_out(float* __restrict__ out, int S) {
    int row = blockIdx.x * 8 + (threadIdx.x >> 5);
    int lane = threadIdx.x & 31;
    size_t base = (size_t)row * S;
    float m1 = g_pm[base + lane], m2 = g_pm[base + lane + 32];
    float l1 = g_pl[base + lane], l2 = g_pl[base + lane + 32];
    float w1 = g_pw[base + lane], w2 = g_pw[base + lane + 32];
    float M = fmaxf(m1, m2);
#pragma unroll
    for (int o = 16; o > 0; o >>= 1)
        M = fmaxf(M, __shfl_xor_sync(0xFFFFFFFF, M, o));
    float L = l1 * __expf(m1 - M) + l2 * __expf(m2 - M);
    float W = w1 * __expf(m1 - M) + w2 * __expf(m2 - M);
#pragma unroll
    for (int o = 16; o > 0; o >>= 1) {
        L += __shfl_xor_sync(0xFFFFFFFF, L, o);
        W += __shfl_xor_sync(0xFFFFFFFF, W, o);
    }
    if (lane == 0) {
        float r = W / L;
        out[row] = fminf(fmaxf(r, 0.f), 1.f);
    }
}

// ===========================================================================
// Host launcher
// ===========================================================================
extern "C" void kernel_launch(void* const* d_in, const int* in_sizes, int n_in,
                              void* d_out, int out_size)
{
    const float* x   = (const float*)d_in[0];
    const float* xn  = (const float*)d_in[1];
    const float* y   = (const float*)d_in[2];
    const float* Ws[3] = {(const float*)d_in[3], (const float*)d_in[7], (const float*)d_in[11]};
    const float* bs[3] = {(const float*)d_in[4], (const float*)d_in[8], (const float*)d_in[12]};
    const float* gs[3] = {(const float*)d_in[5], (const float*)d_in[9], (const float*)d_in[13]};
    const float* es[3] = {(const float*)d_in[6], (const float*)d_in[10], (const float*)d_in[14]};

    const int D  = in_sizes[5];          // 1024
    const int B  = in_sizes[0] / D;      // 4096
    const int N  = in_sizes[2];          // 8192
    const int dims[4] = {D, in_sizes[4], in_sizes[8], in_sizes[12]}; // 1024,1024,512,256

    __nv_bfloat16 *p1h, *p1l, *p2h, *p2l, *wth, *wtl, *qh, *ql, *kh, *kl;
    float *gsum, *gsumsq, *gk2;
    cudaGetSymbolAddress((void**)&p1h, g_P1h); cudaGetSymbolAddress((void**)&p1l, g_P1l);
    cudaGetSymbolAddress((void**)&p2h, g_P2h); cudaGetSymbolAddress((void**)&p2l, g_P2l);
    cudaGetSymbolAddress((void**)&wth, g_WTh); cudaGetSymbolAddress((void**)&wtl, g_WTl);
    cudaGetSymbolAddress((void**)&qh, g_qh);   cudaGetSymbolAddress((void**)&ql, g_ql);
    cudaGetSymbolAddress((void**)&kh, g_kh);   cudaGetSymbolAddress((void**)&kl, g_kl);
    cudaGetSymbolAddress((void**)&gsum, g_sum);
    cudaGetSymbolAddress((void**)&gsumsq, g_sumsq);
    cudaGetSymbolAddress((void**)&gk2, g_k2);

    cudaFuncSetAttribute(gemm_trunk, cudaFuncAttributeMaxDynamicSharedMemorySize, GEMM_SMEM);
    cudaFuncSetAttribute(sim_flash, cudaFuncAttributeMaxDynamicSharedMemorySize, GEMM_SMEM);

    auto run_branch = [&](const float* X, int R,
                          __nv_bfloat16* outh, __nv_bfloat16* outl, int last_accum) {
        zero_two<<<4, 256>>>(gsum, gsumsq, dims[0]);
        split_stats<<<dim3(dims[0] / 256, 64), 256>>>(X, p1h, p1l, R, dims[0]);

        __nv_bfloat16* ih = p1h; __nv_bfloat16* il = p1l;
        __nv_bfloat16* oh = p2h; __nv_bfloat16* ol = p2l;
        for (int i = 0; i < 3; ++i) {
            int Din = dims[i], Dout = dims[i + 1];
            int mx = Din > Dout ? Din : Dout;
            finalize_bias<<<(mx + 255) / 256, 256>>>(R, Din, Dout, gs[i], es[i], bs[i]);
            wprep_bias<<<dim3(Dout / 32, Din / 32), dim3(32, 8)>>>(Ws[i], Din, Dout, wth, wtl);
            int accum = (i < 2) ? 1 : last_accum;
            __nv_bfloat16* th = (i == 2) ? outh : oh;
            __nv_bfloat16* tl = (i == 2) ? outl : ol;
            gemm_trunk<<<dim3(Dout / 128, R / 128), 128, GEMM_SMEM>>>(
                ih, il, wth, wtl, Din, Dout, accum, th, tl);
            __nv_bfloat16* sh = ih; __nv_bfloat16* sl = il;
            ih = oh; il = ol; oh = sh; ol = sl;
        }
    };

    run_branch(x, B, qh, ql, 0);
    zero_one<<<(N + 255) / 256, 256>>>(gk2, N);
    run_branch(xn, N, kh, kl, 2);   // layer-3 epilogue accumulates g_k2

    const int NSPLIT = N / 128;     // 64
    sim_flash<<<dim3(NSPLIT, B / 128), 128, GEMM_SMEM>>>(
        qh, ql, kh, kl, y, dims[3], NSPLIT);
    combine_out<<<B / 8, 256>>>((float*)d_out, NSPLIT);
}

// round 7
// speedup vs baseline: 1.1778x; 1.1778x over previous
#include <cuda_runtime.h>
#include <cuda_bf16.h>
#include <math.h>
#include <stdint.h>

// ===========================================================================
// Static scratch (B=4096, N=8192, D<=1024 fixed by dataset)
// ===========================================================================
__device__ float g_sum[1024];
__device__ float g_sumsq[1024];
__device__ float g_a[1024];
__device__ float g_dd[1024];
__device__ float g_bias2[1024];
__device__ float g_k2[8192];
__device__ __nv_bfloat16 g_P1h[8192 * 1024], g_P1l[8192 * 1024];
__device__ __nv_bfloat16 g_P2h[8192 * 1024], g_P2l[8192 * 1024];
__device__ __nv_bfloat16 g_WTh[1024 * 1024], g_WTl[1024 * 1024];
__device__ __nv_bfloat16 g_qh[4096 * 256], g_ql[4096 * 256];
__device__ __nv_bfloat16 g_kh[8192 * 256], g_kl[8192 * 256];
__device__ float g_pm[4096 * 64], g_pl[4096 * 64], g_pw[4096 * 64];

// ===========================================================================
// Prep kernels
// ===========================================================================
__global__ void zero_two(float* a, float* b, int n) {
    int i = blockIdx.x * blockDim.x + threadIdx.x;
    if (i < n) { a[i] = 0.f; b[i] = 0.f; }
}
__global__ void zero_one(float* a, int n) {
    int i = blockIdx.x * blockDim.x + threadIdx.x;
    if (i < n) a[i] = 0.f;
}

// fp32 -> bf16 hi/lo split + column stats accumulation (layer-1 input)
__global__ void split_stats(const float* __restrict__ X,
                            __nv_bfloat16* __restrict__ hi,
                            __nv_bfloat16* __restrict__ lo,
                            int R, int Din) {
    int c = blockIdx.x * blockDim.x + threadIdx.x;
    if (c >= Din) return;
    int chunk = R / gridDim.y;
    int r0 = blockIdx.y * chunk;
    float s = 0.f, s2 = 0.f;
    for (int r = r0; r < r0 + chunk; ++r) {
        size_t i = (size_t)r * Din + c;
        float v = X[i];
        __nv_bfloat16 h = __float2bfloat16(v);
        hi[i] = h;
        lo[i] = __float2bfloat16(v - __bfloat162float(h));
        s += v;
        s2 = fmaf(v, v, s2);
    }
    atomicAdd(&g_sum[c], s);
    atomicAdd(&g_sumsq[c], s2);
}

// finalize BN stats (Din) + init bias2 (Dout) + zero stats for next layer
__global__ void finalize_bias(int R, int Din, int Dout,
                              const float* __restrict__ gam,
                              const float* __restrict__ bet,
                              const float* __restrict__ b) {
    int c = blockIdx.x * blockDim.x + threadIdx.x;
    if (c < Din) {
        float inv = 1.0f / (float)R;
        float mean = g_sum[c] * inv;
        float var = g_sumsq[c] * inv - mean * mean;
        float a = gam[c] * rsqrtf(var + 1e-5f);
        g_a[c] = a;
        g_dd[c] = bet[c] - mean * a;
    }
    if (c < Dout) {
        g_bias2[c] = b[c];
        g_sum[c] = 0.f;
        g_sumsq[c] = 0.f;
    }
}

// WT[n,k] = a[k]*W[k,n] split to bf16 hi/lo (transpose) + bias2 accumulation
__global__ void wprep_bias(const float* __restrict__ W, int Din, int Dout,
                           __nv_bfloat16* __restrict__ WTh,
                           __nv_bfloat16* __restrict__ WTl) {
    __shared__ float tile[32][33];
    __shared__ float sbias[8][32];
    int k0 = blockIdx.y * 32, n0 = blockIdx.x * 32;
    int tx = threadIdx.x, ty = threadIdx.y;
    float bp = 0.f;
    for (int i = ty; i < 32; i += 8) {
        float w = W[(size_t)(k0 + i) * Dout + n0 + tx];
        tile[i][tx] = g_a[k0 + i] * w;
        bp = fmaf(g_dd[k0 + i], w, bp);
    }
    sbias[ty][tx] = bp;
    __syncthreads();
    if (ty == 0) {
        float s = 0.f;
#pragma unroll
        for (int j = 0; j < 8; ++j) s += sbias[j][tx];
        atomicAdd(&g_bias2[n0 + tx], s);
    }
    for (int i = ty; i < 32; i += 8) {
        float v = tile[tx][i];
        size_t idx = (size_t)(n0 + i) * Din + (k0 + tx);
        __nv_bfloat16 h = __float2bfloat16(v);
        WTh[idx] = h;
        WTl[idx] = __float2bfloat16(v - __bfloat162float(h));
    }
}

// ===========================================================================
// GEMM machinery (R4 config): CTA 128x128, K-tile 32, 2-stage cp.async,
// 8 warps (2x4), warp tile 64x32, scalar LDS fragment loads, 256 thr,
// 2 CTA/SM, 3-product bf16 emulation.
// ===========================================================================
#define LDKB 80                 // smem bytes per row (32 bf16 + 8B pad)
#define TILE_B (128 * LDKB)     // 10240 B
#define STAGE_B (4 * TILE_B)    // 40960 B (Ah,Al,Bh,Bl)
#define GEMM_SMEM (2 * STAGE_B) // 81920 B

__device__ __forceinline__ void mma_bf16(float* d, const uint32_t* a, const uint32_t* b) {
    asm volatile("mma.sync.aligned.m16n8k16.row.col.f32.bf16.bf16.f32 "
        "{%0,%1,%2,%3}, {%4,%5,%6,%7}, {%8,%9}, {%0,%1,%2,%3};"
        : "+f"(d[0]), "+f"(d[1]), "+f"(d[2]), "+f"(d[3])
        : "r"(a[0]), "r"(a[1]), "r"(a[2]), "r"(a[3]), "r"(b[0]), "r"(b[1]));
}

#define FILL_TILE(t, s)                                                        \
    do {                                                                       \
        char* base_ = smem + (s) * STAGE_B;                                    \
        const int k0_ = (t) << 5;                                              \
        _Pragma("unroll")                                                      \
        for (int l_ = 0; l_ < 8; ++l_) {                                       \
            int id_ = tid + (l_ << 8);                                         \
            int which_ = id_ >> 9;                                             \
            int e_ = id_ & 511;                                                \
            int row_ = e_ >> 2, c4_ = e_ & 3;                                  \
            const __nv_bfloat16* src_ =                                        \
                (which_ == 0) ? Ah : (which_ == 1) ? Al : (which_ == 2) ? Bh : Bl; \
            int grow_ = ((which_ < 2) ? m0 : n0) + row_;                       \
            const char* gp_ = (const char*)(src_ + (size_t)grow_ * K + k0_) + (c4_ << 4); \
            uint32_t sp_ = (uint32_t)__cvta_generic_to_shared(                 \
                base_ + which_ * TILE_B + row_ * LDKB + (c4_ << 4));           \
            asm volatile("cp.async.cg.shared.global [%0], [%1], 16;" :: "r"(sp_), "l"(gp_)); \
        }                                                                      \
        asm volatile("cp.async.commit_group;");                                \
    } while (0)

#define MMA_MAINLOOP()                                                         \
    do {                                                                       \
        FILL_TILE(0, 0);                                                       \
        for (int t = 0; t < T; ++t) {                                          \
            if (t + 1 < T) {                                                   \
                FILL_TILE(t + 1, (t + 1) & 1);                                 \
                asm volatile("cp.async.wait_group 1;");                        \
            } else {                                                           \
                asm volatile("cp.async.wait_group 0;");                        \
            }                                                                  \
            __syncthreads();                                                   \
            const char* st_ = smem + (t & 1) * STAGE_B;                        \
            _Pragma("unroll")                                                  \
            for (int kk = 0; kk < 2; ++kk) {                                   \
                const int kb_ = (kk << 4) + cc;                                \
                uint32_t bh_[4][2], bl_[4][2];                                 \
                _Pragma("unroll")                                              \
                for (int nt = 0; nt < 4; ++nt) {                               \
                    const char* pB_ = st_ + 2 * TILE_B + (wn * 32 + nt * 8 + g) * LDKB + kb_ * 2; \
                    bh_[nt][0] = *(const uint32_t*)pB_;                        \
                    bh_[nt][1] = *(const uint32_t*)(pB_ + 16);                 \
                    bl_[nt][0] = *(const uint32_t*)(pB_ + TILE_B);             \
                    bl_[nt][1] = *(const uint32_t*)(pB_ + TILE_B + 16);        \
                }                                                              \
                _Pragma("unroll")                                              \
                for (int mt = 0; mt < 4; ++mt) {                               \
                    const char* pA_ = st_ + (wm * 64 + mt * 16 + g) * LDKB + kb_ * 2; \
                    uint32_t ah_[4], al_[4];                                   \
                    ah_[0] = *(const uint32_t*)pA_;                            \
                    ah_[1] = *(const uint32_t*)(pA_ + 8 * LDKB);               \
                    ah_[2] = *(const uint32_t*)(pA_ + 16);                     \
                    ah_[3] = *(const uint32_t*)(pA_ + 8 * LDKB + 16);          \
                    al_[0] = *(const uint32_t*)(pA_ + TILE_B);                 \
                    al_[1] = *(const uint32_t*)(pA_ + TILE_B + 8 * LDKB);      \
                    al_[2] = *(const uint32_t*)(pA_ + TILE_B + 16);            \
                    al_[3] = *(const uint32_t*)(pA_ + TILE_B + 8 * LDKB + 16); \
                    _Pragma("unroll")                                          \
                    for (int nt = 0; nt < 4; ++nt) {                           \
                        mma_bf16(acc[mt][nt], ah_, bh_[nt]);                   \
                        mma_bf16(acc[mt][nt], ah_, bl_[nt]);                   \
                        mma_bf16(acc[mt][nt], al_, bh_[nt]);                   \
                    }                                                          \
                }                                                              \
            }                                                                  \
            __syncthreads();                                                   \
        }                                                                      \
    } while (0)

#define GEMM_PREAMBLE()                                                        \
    const int tid = threadIdx.x;                                               \
    const int wid = tid >> 5, lane = tid & 31;                                 \
    const int g = lane >> 2;                                                   \
    const int cc = (lane & 3) * 2;                                             \
    const int wm = wid >> 2, wn = wid & 3;                                     \
    const int m0 = blockIdx.y * 128, n0 = blockIdx.x * 128;                    \
    const int T = K >> 5;                                                      \
    float acc[4][4][4];                                                        \
    _Pragma("unroll")                                                          \
    for (int i = 0; i < 4; ++i)                                                \
        _Pragma("unroll")                                                      \
        for (int j = 0; j < 4; ++j)                                            \
            _Pragma("unroll")                                                  \
            for (int r = 0; r < 4; ++r) acc[i][j][r] = 0.f;

// ===========================================================================
// Trunk GEMM: Y = tanh((Ah+Al)@(Bh+Bl)^T + bias2) -> bf16 hi/lo
// accum 1: + column stats of tanh into g_sum/g_sumsq
// accum 2: + row sumsq of tanh into g_k2
// ===========================================================================
__global__ __launch_bounds__(256, 2) void gemm_trunk(
    const __nv_bfloat16* __restrict__ Ah, const __nv_bfloat16* __restrict__ Al,
    const __nv_bfloat16* __restrict__ Bh, const __nv_bfloat16* __restrict__ Bl,
    int K, int ldOut, int accum,
    __nv_bfloat16* __restrict__ Yh, __nv_bfloat16* __restrict__ Yl)
{
    extern __shared__ __align__(16) char smem[];
    GEMM_PREAMBLE();
    MMA_MAINLOOP();

    float* s_sum = (float*)smem;
    float* s_sq  = (float*)smem + 128;
    if (accum) {
        if (tid < 128) { s_sum[tid] = 0.f; s_sq[tid] = 0.f; }
        __syncthreads();
    }

#pragma unroll
    for (int mt = 0; mt < 4; ++mt) {
#pragma unroll
        for (int nt = 0; nt < 4; ++nt) {
            int row = m0 + wm * 64 + mt * 16 + g;
            int col = n0 + wn * 32 + nt * 8 + cc;
            float* a = acc[mt][nt];
            float bA = g_bias2[col], bB = g_bias2[col + 1];
#pragma unroll
            for (int h = 0; h < 2; ++h) {
                int r = row + h * 8;
                float v0 = tanhf(a[h * 2 + 0] + bA);
                float v1 = tanhf(a[h * 2 + 1] + bB);
                a[h * 2 + 0] = v0;
                a[h * 2 + 1] = v1;
                __nv_bfloat162 hp, lp;
                hp.x = __float2bfloat16(v0);
                hp.y = __float2bfloat16(v1);
                lp.x = __float2bfloat16(v0 - __bfloat162float(hp.x));
                lp.y = __float2bfloat16(v1 - __bfloat162float(hp.y));
                *(uint32_t*)(Yh + (size_t)r * ldOut + col) = *(uint32_t*)&hp;
                *(uint32_t*)(Yl + (size_t)r * ldOut + col) = *(uint32_t*)&lp;
            }
        }
    }

    if (accum == 1) {
#pragma unroll
        for (int nt = 0; nt < 4; ++nt) {
            int lc = wn * 32 + nt * 8 + cc;
            float s0 = 0.f, q0 = 0.f, s1 = 0.f, q1 = 0.f;
#pragma unroll
            for (int mt = 0; mt < 4; ++mt) {
                float* a = acc[mt][nt];
#pragma unroll
                for (int h = 0; h < 2; ++h) {
                    s0 += a[h * 2 + 0]; q0 = fmaf(a[h * 2 + 0], a[h * 2 + 0], q0);
                    s1 += a[h * 2 + 1]; q1 = fmaf(a[h * 2 + 1], a[h * 2 + 1], q1);
                }
            }
            atomicAdd(&s_sum[lc], s0);     atomicAdd(&s_sq[lc], q0);
            atomicAdd(&s_sum[lc + 1], s1); atomicAdd(&s_sq[lc + 1], q1);
        }
        __syncthreads();
        if (tid < 128) {
            atomicAdd(&g_sum[n0 + tid], s_sum[tid]);
            atomicAdd(&g_sumsq[n0 + tid], s_sq[tid]);
        }
    } else if (accum == 2) {
#pragma unroll
        for (int mt = 0; mt < 4; ++mt) {
#pragma unroll
            for (int h = 0; h < 2; ++h) {
                int lr = wm * 64 + mt * 16 + h * 8 + g;
                float s = 0.f;
#pragma unroll
                for (int nt = 0; nt < 4; ++nt) {
                    float v0 = acc[mt][nt][h * 2 + 0];
                    float v1 = acc[mt][nt][h * 2 + 1];
                    s = fmaf(v0, v0, s);
                    s = fmaf(v1, v1, s);
                }
                atomicAdd(&s_sum[lr], s);
            }
        }
        __syncthreads();
        if (tid < 128) atomicAdd(&g_k2[m0 + tid], s_sum[tid]);
    }
}

// ===========================================================================
// Flash sim+softmax: 128x128 logits (2*q.k - k2), partial softmax with
// y-weighting -> (max, expsum, wsum) per row per key-split.
// ===========================================================================
__global__ __launch_bounds__(256, 2) void sim_flash(
    const __nv_bfloat16* __restrict__ Ah, const __nv_bfloat16* __restrict__ Al,
    const __nv_bfloat16* __restrict__ Bh, const __nv_bfloat16* __restrict__ Bl,
    const float* __restrict__ y, int K, int nsplit)
{
    extern __shared__ __align__(16) char smem[];
    GEMM_PREAMBLE();
    MMA_MAINLOOP();

    float yv[4][2], k2v[4][2];
#pragma unroll
    for (int nt = 0; nt < 4; ++nt) {
        int col = n0 + wn * 32 + nt * 8 + cc;
        yv[nt][0] = y[col];     yv[nt][1] = y[col + 1];
        k2v[nt][0] = g_k2[col]; k2v[nt][1] = g_k2[col + 1];
    }

    float* red = (float*)smem;   // [128 rows][4 wn][3]
#pragma unroll
    for (int mt = 0; mt < 4; ++mt) {
#pragma unroll
        for (int h = 0; h < 2; ++h) {
            float lg[4][2];
            float mx = -3.4e38f;
#pragma unroll
            for (int nt = 0; nt < 4; ++nt) {
#pragma unroll
                for (int c2 = 0; c2 < 2; ++c2) {
                    float v = 2.f * acc[mt][nt][h * 2 + c2] - k2v[nt][c2];
                    lg[nt][c2] = v;
                    mx = fmaxf(mx, v);
                }
            }
            mx = fmaxf(mx, __shfl_xor_sync(0xFFFFFFFF, mx, 1));
            mx = fmaxf(mx, __shfl_xor_sync(0xFFFFFFFF, mx, 2));
            float s = 0.f, w = 0.f;
#pragma unroll
            for (int nt = 0; nt < 4; ++nt) {
#pragma unroll
                for (int c2 = 0; c2 < 2; ++c2) {
                    float e = __expf(lg[nt][c2] - mx);
                    s += e;
                    w = fmaf(e, yv[nt][c2], w);
                }
            }
            s += __shfl_xor_sync(0xFFFFFFFF, s, 1);
            s += __shfl_xor_sync(0xFFFFFFFF, s, 2);
            w += __shfl_xor_sync(0xFFFFFFFF, w, 1);
            w += __shfl_xor_sync(0xFFFFFFFF, w, 2);
            if ((lane & 3) == 0) {
                int lr = wm * 64 + mt * 16 + h * 8 + g;
                red[(lr * 4 + wn) * 3 + 0] = mx;
                red[(lr * 4 + wn) * 3 + 1] = s;
                red[(lr * 4 + wn) * 3 + 2] = w;
            }
        }
    }
    __syncthreads();
    if (tid < 128) {
        float M = -3.4e38f;
#pragma unroll
        for (int j = 0; j < 4; ++j) M = fmaxf(M, red[(tid * 4 + j) * 3 + 0]);
        float L = 0.f, W = 0.f;
#pragma unroll
        for (int j = 0; j < 4; ++j) {
            float e = __expf(red[(tid * 4 + j) * 3 + 0] - M);
            L = fmaf(red[(tid * 4 + j) * 3 + 1], e, L);
            W = fmaf(red[(tid * 4 + j) * 3 + 2], e, W);
        }
        size_t idx = (size_t)(m0 + tid) * nsplit + blockIdx.x;
        g_pm[idx] = M;
        g_pl[idx] = L;
        g_pw[idx] = W;
    }
}

// ===========================================================================
// Combine partials: out[row] = clip( W/L ), log-sum-exp merge over 64 splits
// ===========================================================================
__global__ void combine_out(float* __restrict__ out, int S) {
    int row = blockIdx.x * 8 + (threadIdx.x >> 5);
    int lane = threadIdx.x & 31;
    size_t base = (size_t)row * S;
    float m1 = g_pm[base + lane], m2 = g_pm[base + lane + 32];
    float l1 = g_pl[base + lane], l2 = g_pl[base + lane + 32];
    float w1 = g_pw[base + lane], w2 = g_pw[base + lane + 32];
    float M = fmaxf(m1, m2);
#pragma unroll
    for (int o = 16; o > 0; o >>= 1)
        M = fmaxf(M, __shfl_xor_sync(0xFFFFFFFF, M, o));
    float L = l1 * __expf(m1 - M) + l2 * __expf(m2 - M);
    float W = w1 * __expf(m1 - M) + w2 * __expf(m2 - M);
#pragma unroll
    for (int o = 16; o > 0; o >>= 1) {
        L += __shfl_xor_sync(0xFFFFFFFF, L, o);
        W += __shfl_xor_sync(0xFFFFFFFF, W, o);
    }
    if (lane == 0) {
        float r = W / L;
        out[row] = fminf(fmaxf(r, 0.f), 1.f);
    }
}

// ===========================================================================
// Host launcher
// ===========================================================================
extern "C" void kernel_launch(void* const* d_in, const int* in_sizes, int n_in,
                              void* d_out, int out_size)
{
    const float* x   = (const float*)d_in[0];
    const float* xn  = (const float*)d_in[1];
    const float* y   = (const float*)d_in[2];
    const float* Ws[3] = {(const float*)d_in[3], (const float*)d_in[7], (const float*)d_in[11]};
    const float* bs[3] = {(const float*)d_in[4], (const float*)d_in[8], (const float*)d_in[12]};
    const float* gs[3] = {(const float*)d_in[5], (const float*)d_in[9], (const float*)d_in[13]};
    const float* es[3] = {(const float*)d_in[6], (const float*)d_in[10], (const float*)d_in[14]};

    const int D  = in_sizes[5];          // 1024
    const int B  = in_sizes[0] / D;      // 4096
    const int N  = in_sizes[2];          // 8192
    const int dims[4] = {D, in_sizes[4], in_sizes[8], in_sizes[12]}; // 1024,1024,512,256

    __nv_bfloat16 *p1h, *p1l, *p2h, *p2l, *wth, *wtl, *qh, *ql, *kh, *kl;
    float *gsum, *gsumsq, *gk2;
    cudaGetSymbolAddress((void**)&p1h, g_P1h); cudaGetSymbolAddress((void**)&p1l, g_P1l);
    cudaGetSymbolAddress((void**)&p2h, g_P2h); cudaGetSymbolAddress((void**)&p2l, g_P2l);
    cudaGetSymbolAddress((void**)&wth, g_WTh); cudaGetSymbolAddress((void**)&wtl, g_WTl);
    cudaGetSymbolAddress((void**)&qh, g_qh);   cudaGetSymbolAddress((void**)&ql, g_ql);
    cudaGetSymbolAddress((void**)&kh, g_kh);   cudaGetSymbolAddress((void**)&kl, g_kl);
    cudaGetSymbolAddress((void**)&gsum, g_sum);
    cudaGetSymbolAddress((void**)&gsumsq, g_sumsq);
    cudaGetSymbolAddress((void**)&gk2, g_k2);

    cudaFuncSetAttribute(gemm_trunk, cudaFuncAttributeMaxDynamicSharedMemorySize, GEMM_SMEM);
    cudaFuncSetAttribute(sim_flash, cudaFuncAttributeMaxDynamicSharedMemorySize, GEMM_SMEM);

    auto run_branch = [&](const float* X, int R,
                          __nv_bfloat16* outh, __nv_bfloat16* outl, int last_accum) {
        zero_two<<<4, 256>>>(gsum, gsumsq, dims[0]);
        split_stats<<<dim3(dims[0] / 256, 64), 256>>>(X, p1h, p1l, R, dims[0]);

        __nv_bfloat16* ih = p1h; __nv_bfloat16* il = p1l;
        __nv_bfloat16* oh = p2h; __nv_bfloat16* ol = p2l;
        for (int i = 0; i < 3; ++i) {
            int Din = dims[i], Dout = dims[i + 1];
            int mx = Din > Dout ? Din : Dout;
            finalize_bias<<<(mx + 255) / 256, 256>>>(R, Din, Dout, gs[i], es[i], bs[i]);
            wprep_bias<<<dim3(Dout / 32, Din / 32), dim3(32, 8)>>>(Ws[i], Din, Dout, wth, wtl);
            int accum = (i < 2) ? 1 : last_accum;
            __nv_bfloat16* th = (i == 2) ? outh : oh;
            __nv_bfloat16* tl = (i == 2) ? outl : ol;
            gemm_trunk<<<dim3(Dout / 128, R / 128), 256, GEMM_SMEM>>>(
                ih, il, wth, wtl, Din, Dout, accum, th, tl);
            __nv_bfloat16* sh = ih; __nv_bfloat16* sl = il;
            ih = oh; il = ol; oh = sh; ol = sl;
        }
    };

    run_branch(x, B, qh, ql, 0);
    zero_one<<<(N + 255) / 256, 256>>>(gk2, N);
    run_branch(xn, N, kh, kl, 2);   // layer-3 epilogue accumulates g_k2

    const int NSPLIT = N / 128;     // 64
    sim_flash<<<dim3(NSPLIT, B / 128), 256, GEMM_SMEM>>>(
        qh, ql, kh, kl, y, dims[3], NSPLIT);
    combine_out<<<B / 8, 256>>>((float*)d_out, NSPLIT);
}

// round 8
// speedup vs baseline: 1.2246x; 1.0397x over previous
#include <cuda_runtime.h>
#include <cuda_bf16.h>
#include <math.h>
#include <stdint.h>

// ===========================================================================
// Static scratch. Branch 0 = q (B=4096 rows), branch 1 = k (N=8192 rows).
// Per-branch arrays are [2][1024] flattened.
// ===========================================================================
__device__ float g_sum[2048];
__device__ float g_sumsq[2048];
__device__ float g_a[2048];
__device__ float g_dd[2048];
__device__ float g_bias2[2048];
__device__ float g_k2[8192];
// q-branch ping-pong activations
__device__ __nv_bfloat16 g_Q1h[4096 * 1024], g_Q1l[4096 * 1024];
__device__ __nv_bfloat16 g_Q2h[4096 * 1024], g_Q2l[4096 * 1024];
// k-branch ping-pong activations
__device__ __nv_bfloat16 g_P1h[8192 * 1024], g_P1l[8192 * 1024];
__device__ __nv_bfloat16 g_P2h[8192 * 1024], g_P2l[8192 * 1024];
// per-branch prepped weights (transposed, BN-scaled, split)
__device__ __nv_bfloat16 g_WT0h[1024 * 1024], g_WT0l[1024 * 1024];
__device__ __nv_bfloat16 g_WT1h[1024 * 1024], g_WT1l[1024 * 1024];
// final trunk outputs
__device__ __nv_bfloat16 g_qh[4096 * 256], g_ql[4096 * 256];
__device__ __nv_bfloat16 g_kh[8192 * 256], g_kl[8192 * 256];
// flash-softmax partials
__device__ float g_pm[4096 * 64], g_pl[4096 * 64], g_pw[4096 * 64];

// ===========================================================================
// Prep kernels
// ===========================================================================
__global__ void zero_all() {
    int i = blockIdx.x * blockDim.x + threadIdx.x;
    if (i < 2048) { g_sum[i] = 0.f; g_sumsq[i] = 0.f; }
    if (i < 8192) g_k2[i] = 0.f;
}

// fp32 -> bf16 hi/lo split + column stats, both branches (z picks branch)
__global__ void split_stats(const float* __restrict__ x,
                            const float* __restrict__ xn,
                            __nv_bfloat16* __restrict__ qhi, __nv_bfloat16* __restrict__ qlo,
                            __nv_bfloat16* __restrict__ khi, __nv_bfloat16* __restrict__ klo,
                            int Rq, int Rk, int Din) {
    int z = blockIdx.z;
    const float* X = z ? xn : x;
    __nv_bfloat16* hi = z ? khi : qhi;
    __nv_bfloat16* lo = z ? klo : qlo;
    int R = z ? Rk : Rq;
    int c = blockIdx.x * blockDim.x + threadIdx.x;
    if (c >= Din) return;
    int chunk = R / gridDim.y;
    int r0 = blockIdx.y * chunk;
    float s = 0.f, s2 = 0.f;
    for (int r = r0; r < r0 + chunk; ++r) {
        size_t i = (size_t)r * Din + c;
        float v = X[i];
        __nv_bfloat16 h = __float2bfloat16(v);
        hi[i] = h;
        lo[i] = __float2bfloat16(v - __bfloat162float(h));
        s += v;
        s2 = fmaf(v, v, s2);
    }
    atomicAdd(&g_sum[z * 1024 + c], s);
    atomicAdd(&g_sumsq[z * 1024 + c], s2);
}

// finalize BN stats (Din) + init bias2 (Dout) + zero stats for next layer.
// grid.y = branch.
__global__ void finalize_bias(int Rq, int Rk, int Din, int Dout,
                              const float* __restrict__ gam,
                              const float* __restrict__ bet,
                              const float* __restrict__ b) {
    int z = blockIdx.y;
    int off = z * 1024;
    int R = z ? Rk : Rq;
    int c = blockIdx.x * blockDim.x + threadIdx.x;
    if (c < Din) {
        float inv = 1.0f / (float)R;
        float mean = g_sum[off + c] * inv;
        float var = g_sumsq[off + c] * inv - mean * mean;
        float a = gam[c] * rsqrtf(var + 1e-5f);
        g_a[off + c] = a;
        g_dd[off + c] = bet[c] - mean * a;
    }
    if (c < Dout) {
        g_bias2[off + c] = b[c];
        g_sum[off + c] = 0.f;
        g_sumsq[off + c] = 0.f;
    }
}

// Both branches: WT_z[n,k] = a_z[k]*W[k,n] split bf16 hi/lo + bias2_z accum.
// Reads W once. 32x32 tiles, 32x8 threads.
__global__ void wprep_both(const float* __restrict__ W, int Din, int Dout,
                           __nv_bfloat16* __restrict__ W0h, __nv_bfloat16* __restrict__ W0l,
                           __nv_bfloat16* __restrict__ W1h, __nv_bfloat16* __restrict__ W1l) {
    __shared__ float t0[32][33], t1[32][33];
    __shared__ float sb0[8][32], sb1[8][32];
    int k0 = blockIdx.y * 32, n0 = blockIdx.x * 32;
    int tx = threadIdx.x, ty = threadIdx.y;
    float bp0 = 0.f, bp1 = 0.f;
    for (int i = ty; i < 32; i += 8) {
        float w = W[(size_t)(k0 + i) * Dout + n0 + tx];
        t0[i][tx] = g_a[k0 + i] * w;
        t1[i][tx] = g_a[1024 + k0 + i] * w;
        bp0 = fmaf(g_dd[k0 + i], w, bp0);
        bp1 = fmaf(g_dd[1024 + k0 + i], w, bp1);
    }
    sb0[ty][tx] = bp0;
    sb1[ty][tx] = bp1;
    __syncthreads();
    if (ty == 0) {
        float s0 = 0.f, s1 = 0.f;
#pragma unroll
        for (int j = 0; j < 8; ++j) { s0 += sb0[j][tx]; s1 += sb1[j][tx]; }
        atomicAdd(&g_bias2[n0 + tx], s0);
        atomicAdd(&g_bias2[1024 + n0 + tx], s1);
    }
    for (int i = ty; i < 32; i += 8) {
        size_t idx = (size_t)(n0 + i) * Din + (k0 + tx);
        float v0 = t0[tx][i], v1 = t1[tx][i];
        __nv_bfloat16 h0 = __float2bfloat16(v0);
        W0h[idx] = h0;
        W0l[idx] = __float2bfloat16(v0 - __bfloat162float(h0));
        __nv_bfloat16 h1 = __float2bfloat16(v1);
        W1h[idx] = h1;
        W1l[idx] = __float2bfloat16(v1 - __bfloat162float(h1));
    }
}

// ===========================================================================
// GEMM machinery (R4/R7 config): CTA 128x128, K-tile 32, 2-stage cp.async,
// 8 warps (2x4), warp tile 64x32, scalar LDS, 256 thr, 2 CTA/SM,
// 3-product bf16 emulation.
// ===========================================================================
#define LDKB 80
#define TILE_B (128 * LDKB)
#define STAGE_B (4 * TILE_B)
#define GEMM_SMEM (2 * STAGE_B)

__device__ __forceinline__ void mma_bf16(float* d, const uint32_t* a, const uint32_t* b) {
    asm volatile("mma.sync.aligned.m16n8k16.row.col.f32.bf16.bf16.f32 "
        "{%0,%1,%2,%3}, {%4,%5,%6,%7}, {%8,%9}, {%0,%1,%2,%3};"
        : "+f"(d[0]), "+f"(d[1]), "+f"(d[2]), "+f"(d[3])
        : "r"(a[0]), "r"(a[1]), "r"(a[2]), "r"(a[3]), "r"(b[0]), "r"(b[1]));
}

#define FILL_TILE(t, s)                                                        \
    do {                                                                       \
        char* base_ = smem + (s) * STAGE_B;                                    \
        const int k0_ = (t) << 5;                                              \
        _Pragma("unroll")                                                      \
        for (int l_ = 0; l_ < 8; ++l_) {                                       \
            int id_ = tid + (l_ << 8);                                         \
            int which_ = id_ >> 9;                                             \
            int e_ = id_ & 511;                                                \
            int row_ = e_ >> 2, c4_ = e_ & 3;                                  \
            const __nv_bfloat16* src_ =                                        \
                (which_ == 0) ? Ah : (which_ == 1) ? Al : (which_ == 2) ? Bh : Bl; \
            int grow_ = ((which_ < 2) ? m0 : n0) + row_;                       \
            const char* gp_ = (const char*)(src_ + (size_t)grow_ * K + k0_) + (c4_ << 4); \
            uint32_t sp_ = (uint32_t)__cvta_generic_to_shared(                 \
                base_ + which_ * TILE_B + row_ * LDKB + (c4_ << 4));           \
            asm volatile("cp.async.cg.shared.global [%0], [%1], 16;" :: "r"(sp_), "l"(gp_)); \
        }                                                                      \
        asm volatile("cp.async.commit_group;");                                \
    } while (0)

#define MMA_MAINLOOP()                                                         \
    do {                                                                       \
        FILL_TILE(0, 0);                                                       \
        for (int t = 0; t < T; ++t) {                                          \
            if (t + 1 < T) {                                                   \
                FILL_TILE(t + 1, (t + 1) & 1);                                 \
                asm volatile("cp.async.wait_group 1;");                        \
            } else {                                                           \
                asm volatile("cp.async.wait_group 0;");                        \
            }                                                                  \
            __syncthreads();                                                   \
            const char* st_ = smem + (t & 1) * STAGE_B;                        \
            _Pragma("unroll")                                                  \
            for (int kk = 0; kk < 2; ++kk) {                                   \
                const int kb_ = (kk << 4) + cc;                                \
                uint32_t bh_[4][2], bl_[4][2];                                 \
                _Pragma("unroll")                                              \
                for (int nt = 0; nt < 4; ++nt) {                               \
                    const char* pB_ = st_ + 2 * TILE_B + (wn * 32 + nt * 8 + g) * LDKB + kb_ * 2; \
                    bh_[nt][0] = *(const uint32_t*)pB_;                        \
                    bh_[nt][1] = *(const uint32_t*)(pB_ + 16);                 \
                    bl_[nt][0] = *(const uint32_t*)(pB_ + TILE_B);             \
                    bl_[nt][1] = *(const uint32_t*)(pB_ + TILE_B + 16);        \
                }                                                              \
                _Pragma("unroll")                                              \
                for (int mt = 0; mt < 4; ++mt) {                               \
                    const char* pA_ = st_ + (wm * 64 + mt * 16 + g) * LDKB + kb_ * 2; \
                    uint32_t ah_[4], al_[4];                                   \
                    ah_[0] = *(const uint32_t*)pA_;                            \
                    ah_[1] = *(const uint32_t*)(pA_ + 8 * LDKB);               \
                    ah_[2] = *(const uint32_t*)(pA_ + 16);                     \
                    ah_[3] = *(const uint32_t*)(pA_ + 8 * LDKB + 16);          \
                    al_[0] = *(const uint32_t*)(pA_ + TILE_B);                 \
                    al_[1] = *(const uint32_t*)(pA_ + TILE_B + 8 * LDKB);      \
                    al_[2] = *(const uint32_t*)(pA_ + TILE_B + 16);            \
                    al_[3] = *(const uint32_t*)(pA_ + TILE_B + 8 * LDKB + 16); \
                    _Pragma("unroll")                                          \
                    for (int nt = 0; nt < 4; ++nt) {                           \
                        mma_bf16(acc[mt][nt], ah_, bh_[nt]);                   \
                        mma_bf16(acc[mt][nt], ah_, bl_[nt]);                   \
                        mma_bf16(acc[mt][nt], al_, bh_[nt]);                   \
                    }                                                          \
                }                                                              \
            }                                                                  \
            __syncthreads();                                                   \
        }                                                                      \
    } while (0)

#define GEMM_THREAD_IDS()                                                      \
    const int tid = threadIdx.x;                                               \
    const int wid = tid >> 5, lane = tid & 31;                                 \
    const int g = lane >> 2;                                                   \
    const int cc = (lane & 3) * 2;                                             \
    const int wm = wid >> 2, wn = wid & 3;                                     \
    float acc[4][4][4];                                                        \
    _Pragma("unroll")                                                          \
    for (int i = 0; i < 4; ++i)                                                \
        _Pragma("unroll")                                                      \
        for (int j = 0; j < 4; ++j)                                            \
            _Pragma("unroll")                                                  \
            for (int r = 0; r < 4; ++r) acc[i][j][r] = 0.f;

// ===========================================================================
// Merged trunk GEMM (both branches in one grid).
// Flattened grid: blocks [0, nx*myq) -> branch 0; rest -> branch 1.
// accum 1: column stats of tanh into g_sum[br]; accum 2: row sumsq -> g_k2.
// ===========================================================================
__global__ __launch_bounds__(256, 2) void gemm_trunk2(
    const __nv_bfloat16* __restrict__ Ah0, const __nv_bfloat16* __restrict__ Al0,
    const __nv_bfloat16* __restrict__ Ah1, const __nv_bfloat16* __restrict__ Al1,
    const __nv_bfloat16* __restrict__ Bh0, const __nv_bfloat16* __restrict__ Bl0,
    const __nv_bfloat16* __restrict__ Bh1, const __nv_bfloat16* __restrict__ Bl1,
    int K, int ldOut, int nx, int myq, int accum0, int accum1,
    __nv_bfloat16* __restrict__ Yh0, __nv_bfloat16* __restrict__ Yl0,
    __nv_bfloat16* __restrict__ Yh1, __nv_bfloat16* __restrict__ Yl1)
{
    extern __shared__ __align__(16) char smem[];
    GEMM_THREAD_IDS();

    int id = blockIdx.x;
    int br, tile;
    if (id < nx * myq) { br = 0; tile = id; }
    else               { br = 1; tile = id - nx * myq; }
    const int n0 = (tile % nx) * 128;
    const int m0 = (tile / nx) * 128;
    const int T = K >> 5;
    const __nv_bfloat16* Ah = br ? Ah1 : Ah0;
    const __nv_bfloat16* Al = br ? Al1 : Al0;
    const __nv_bfloat16* Bh = br ? Bh1 : Bh0;
    const __nv_bfloat16* Bl = br ? Bl1 : Bl0;
    __nv_bfloat16* Yh = br ? Yh1 : Yh0;
    __nv_bfloat16* Yl = br ? Yl1 : Yl0;
    const float* bias = g_bias2 + br * 1024;
    const int accum = br ? accum1 : accum0;

    MMA_MAINLOOP();

    float* s_sum = (float*)smem;
    float* s_sq  = (float*)smem + 128;
    if (accum) {
        if (tid < 128) { s_sum[tid] = 0.f; s_sq[tid] = 0.f; }
        __syncthreads();
    }

#pragma unroll
    for (int mt = 0; mt < 4; ++mt) {
#pragma unroll
        for (int nt = 0; nt < 4; ++nt) {
            int row = m0 + wm * 64 + mt * 16 + g;
            int col = n0 + wn * 32 + nt * 8 + cc;
            float* a = acc[mt][nt];
            float bA = bias[col], bB = bias[col + 1];
#pragma unroll
            for (int h = 0; h < 2; ++h) {
                int r = row + h * 8;
                float v0 = tanhf(a[h * 2 + 0] + bA);
                float v1 = tanhf(a[h * 2 + 1] + bB);
                a[h * 2 + 0] = v0;
                a[h * 2 + 1] = v1;
                __nv_bfloat162 hp, lp;
                hp.x = __float2bfloat16(v0);
                hp.y = __float2bfloat16(v1);
                lp.x = __float2bfloat16(v0 - __bfloat162float(hp.x));
                lp.y = __float2bfloat16(v1 - __bfloat162float(hp.y));
                *(uint32_t*)(Yh + (size_t)r * ldOut + col) = *(uint32_t*)&hp;
                *(uint32_t*)(Yl + (size_t)r * ldOut + col) = *(uint32_t*)&lp;
            }
        }
    }

    if (accum == 1) {
#pragma unroll
        for (int nt = 0; nt < 4; ++nt) {
            int lc = wn * 32 + nt * 8 + cc;
            float s0 = 0.f, q0 = 0.f, s1 = 0.f, q1 = 0.f;
#pragma unroll
            for (int mt = 0; mt < 4; ++mt) {
                float* a = acc[mt][nt];
#pragma unroll
                for (int h = 0; h < 2; ++h) {
                    s0 += a[h * 2 + 0]; q0 = fmaf(a[h * 2 + 0], a[h * 2 + 0], q0);
                    s1 += a[h * 2 + 1]; q1 = fmaf(a[h * 2 + 1], a[h * 2 + 1], q1);
                }
            }
            atomicAdd(&s_sum[lc], s0);     atomicAdd(&s_sq[lc], q0);
            atomicAdd(&s_sum[lc + 1], s1); atomicAdd(&s_sq[lc + 1], q1);
        }
        __syncthreads();
        if (tid < 128) {
            atomicAdd(&g_sum[br * 1024 + n0 + tid], s_sum[tid]);
            atomicAdd(&g_sumsq[br * 1024 + n0 + tid], s_sq[tid]);
        }
    } else if (accum == 2) {
#pragma unroll
        for (int mt = 0; mt < 4; ++mt) {
#pragma unroll
            for (int h = 0; h < 2; ++h) {
                int lr = wm * 64 + mt * 16 + h * 8 + g;
                float s = 0.f;
#pragma unroll
                for (int nt = 0; nt < 4; ++nt) {
                    float v0 = acc[mt][nt][h * 2 + 0];
                    float v1 = acc[mt][nt][h * 2 + 1];
                    s = fmaf(v0, v0, s);
                    s = fmaf(v1, v1, s);
                }
                atomicAdd(&s_sum[lr], s);
            }
        }
        __syncthreads();
        if (tid < 128) atomicAdd(&g_k2[m0 + tid], s_sum[tid]);
    }
}

// ===========================================================================
// Flash sim+softmax (unchanged from R7): 128x128 logits, partial softmax
// with y-weighting -> (max, expsum, wsum) per row per key-split.
// ===========================================================================
__global__ __launch_bounds__(256, 2) void sim_flash(
    const __nv_bfloat16* __restrict__ Ah, const __nv_bfloat16* __restrict__ Al,
    const __nv_bfloat16* __restrict__ Bh, const __nv_bfloat16* __restrict__ Bl,
    const float* __restrict__ y, int K, int nsplit)
{
    extern __shared__ __align__(16) char smem[];
    GEMM_THREAD_IDS();
    const int m0 = blockIdx.y * 128, n0 = blockIdx.x * 128;
    const int T = K >> 5;
    MMA_MAINLOOP();

    float yv[4][2], k2v[4][2];
#pragma unroll
    for (int nt = 0; nt < 4; ++nt) {
        int col = n0 + wn * 32 + nt * 8 + cc;
        yv[nt][0] = y[col];     yv[nt][1] = y[col + 1];
        k2v[nt][0] = g_k2[col]; k2v[nt][1] = g_k2[col + 1];
    }

    float* red = (float*)smem;
#pragma unroll
    for (int mt = 0; mt < 4; ++mt) {
#pragma unroll
        for (int h = 0; h < 2; ++h) {
            float lg[4][2];
            float mx = -3.4e38f;
#pragma unroll
            for (int nt = 0; nt < 4; ++nt) {
#pragma unroll
                for (int c2 = 0; c2 < 2; ++c2) {
                    float v = 2.f * acc[mt][nt][h * 2 + c2] - k2v[nt][c2];
                    lg[nt][c2] = v;
                    mx = fmaxf(mx, v);
                }
            }
            mx = fmaxf(mx, __shfl_xor_sync(0xFFFFFFFF, mx, 1));
            mx = fmaxf(mx, __shfl_xor_sync(0xFFFFFFFF, mx, 2));
            float s = 0.f, w = 0.f;
#pragma unroll
            for (int nt = 0; nt < 4; ++nt) {
#pragma unroll
                for (int c2 = 0; c2 < 2; ++c2) {
                    float e = __expf(lg[nt][c2] - mx);
                    s += e;
                    w = fmaf(e, yv[nt][c2], w);
                }
            }
            s += __shfl_xor_sync(0xFFFFFFFF, s, 1);
            s += __shfl_xor_sync(0xFFFFFFFF, s, 2);
            w += __shfl_xor_sync(0xFFFFFFFF, w, 1);
            w += __shfl_xor_sync(0xFFFFFFFF, w, 2);
            if ((lane & 3) == 0) {
                int lr = wm * 64 + mt * 16 + h * 8 + g;
                red[(lr * 4 + wn) * 3 + 0] = mx;
                red[(lr * 4 + wn) * 3 + 1] = s;
                red[(lr * 4 + wn) * 3 + 2] = w;
            }
        }
    }
    __syncthreads();
    if (tid < 128) {
        float M = -3.4e38f;
#pragma unroll
        for (int j = 0; j < 4; ++j) M = fmaxf(M, red[(tid * 4 + j) * 3 + 0]);
        float L = 0.f, W = 0.f;
#pragma unroll
        for (int j = 0; j < 4; ++j) {
            float e = __expf(red[(tid * 4 + j) * 3 + 0] - M);
            L = fmaf(red[(tid * 4 + j) * 3 + 1], e, L);
            W = fmaf(red[(tid * 4 + j) * 3 + 2], e, W);
        }
        size_t idx = (size_t)(m0 + tid) * nsplit + blockIdx.x;
        g_pm[idx] = M;
        g_pl[idx] = L;
        g_pw[idx] = W;
    }
}

// ===========================================================================
// Combine partials: out[row] = clip( W/L ), log-sum-exp merge over 64 splits
// ===========================================================================
__global__ void combine_out(float* __restrict__ out, int S) {
    int row = blockIdx.x * 8 + (threadIdx.x >> 5);
    int lane = threadIdx.x & 31;
    size_t base = (size_t)row * S;
    float m1 = g_pm[base + lane], m2 = g_pm[base + lane + 32];
    float l1 = g_pl[base + lane], l2 = g_pl[base + lane + 32];
    float w1 = g_pw[base + lane], w2 = g_pw[base + lane + 32];
    float M = fmaxf(m1, m2);
#pragma unroll
    for (int o = 16; o > 0; o >>= 1)
        M = fmaxf(M, __shfl_xor_sync(0xFFFFFFFF, M, o));
    float L = l1 * __expf(m1 - M) + l2 * __expf(m2 - M);
    float W = w1 * __expf(m1 - M) + w2 * __expf(m2 - M);
#pragma unroll
    for (int o = 16; o > 0; o >>= 1) {
        L += __shfl_xor_sync(0xFFFFFFFF, L, o);
        W += __shfl_xor_sync(0xFFFFFFFF, W, o);
    }
    if (lane == 0) {
        float r = W / L;
        out[row] = fminf(fmaxf(r, 0.f), 1.f);
    }
}

// ===========================================================================
// Host launcher
// ===========================================================================
extern "C" void kernel_launch(void* const* d_in, const int* in_sizes, int n_in,
                              void* d_out, int out_size)
{
    const float* x   = (const float*)d_in[0];
    const float* xn  = (const float*)d_in[1];
    const float* y   = (const float*)d_in[2];
    const float* Ws[3] = {(const float*)d_in[3], (const float*)d_in[7], (const float*)d_in[11]};
    const float* bs[3] = {(const float*)d_in[4], (const float*)d_in[8], (const float*)d_in[12]};
    const float* gs[3] = {(const float*)d_in[5], (const float*)d_in[9], (const float*)d_in[13]};
    const float* es[3] = {(const float*)d_in[6], (const float*)d_in[10], (const float*)d_in[14]};

    const int D  = in_sizes[5];          // 1024
    const int B  = in_sizes[0] / D;      // 4096
    const int N  = in_sizes[2];          // 8192
    const int dims[4] = {D, in_sizes[4], in_sizes[8], in_sizes[12]}; // 1024,1024,512,256

    __nv_bfloat16 *q1h, *q1l, *q2h, *q2l, *p1h, *p1l, *p2h, *p2l;
    __nv_bfloat16 *w0h, *w0l, *w1h, *w1l, *qh, *ql, *kh, *kl;
    cudaGetSymbolAddress((void**)&q1h, g_Q1h); cudaGetSymbolAddress((void**)&q1l, g_Q1l);
    cudaGetSymbolAddress((void**)&q2h, g_Q2h); cudaGetSymbolAddress((void**)&q2l, g_Q2l);
    cudaGetSymbolAddress((void**)&p1h, g_P1h); cudaGetSymbolAddress((void**)&p1l, g_P1l);
    cudaGetSymbolAddress((void**)&p2h, g_P2h); cudaGetSymbolAddress((void**)&p2l, g_P2l);
    cudaGetSymbolAddress((void**)&w0h, g_WT0h); cudaGetSymbolAddress((void**)&w0l, g_WT0l);
    cudaGetSymbolAddress((void**)&w1h, g_WT1h); cudaGetSymbolAddress((void**)&w1l, g_WT1l);
    cudaGetSymbolAddress((void**)&qh, g_qh);   cudaGetSymbolAddress((void**)&ql, g_ql);
    cudaGetSymbolAddress((void**)&kh, g_kh);   cudaGetSymbolAddress((void**)&kl, g_kl);

    cudaFuncSetAttribute(gemm_trunk2, cudaFuncAttributeMaxDynamicSharedMemorySize, GEMM_SMEM);
    cudaFuncSetAttribute(sim_flash, cudaFuncAttributeMaxDynamicSharedMemorySize, GEMM_SMEM);

    zero_all<<<32, 256>>>();
    split_stats<<<dim3(D / 256, 64, 2), 256>>>(x, xn, q1h, q1l, p1h, p1l, B, N, D);

    // ping-pong pointers per branch
    __nv_bfloat16 *qa_h = q1h, *qa_l = q1l, *qb_h = q2h, *qb_l = q2l;
    __nv_bfloat16 *ka_h = p1h, *ka_l = p1l, *kb_h = p2h, *kb_l = p2l;

    for (int i = 0; i < 3; ++i) {
        int Din = dims[i], Dout = dims[i + 1];
        int mx = Din > Dout ? Din : Dout;
        finalize_bias<<<dim3((mx + 255) / 256, 2), 256>>>(B, N, Din, Dout, gs[i], es[i], bs[i]);
        wprep_both<<<dim3(Dout / 32, Din / 32), dim3(32, 8)>>>(
            Ws[i], Din, Dout, w0h, w0l, w1h, w1l);

        int nx = Dout / 128, myq = B / 128, myk = N / 128;
        int accum0 = (i < 2) ? 1 : 0;
        int accum1 = (i < 2) ? 1 : 2;
        __nv_bfloat16* yq_h = (i == 2) ? qh : qb_h;
        __nv_bfloat16* yq_l = (i == 2) ? ql : qb_l;
        __nv_bfloat16* yk_h = (i == 2) ? kh : kb_h;
        __nv_bfloat16* yk_l = (i == 2) ? kl : kb_l;
        gemm_trunk2<<<nx * (myq + myk), 256, GEMM_SMEM>>>(
            qa_h, qa_l, ka_h, ka_l, w0h, w0l, w1h, w1l,
            Din, Dout, nx, myq, accum0, accum1,
            yq_h, yq_l, yk_h, yk_l);

        // swap ping-pong
        __nv_bfloat16* t;
        t = qa_h; qa_h = qb_h; qb_h = t;  t = qa_l; qa_l = qb_l; qb_l = t;
        t = ka_h; ka_h = kb_h; kb_h = t;  t = ka_l; ka_l = kb_l; kb_l = t;
    }

    const int NSPLIT = N / 128;     // 64
    sim_flash<<<dim3(NSPLIT, B / 128), 256, GEMM_SMEM>>>(
        qh, ql, kh, kl, y, dims[3], NSPLIT);
    combine_out<<<B / 8, 256>>>((float*)d_out, NSPLIT);
}

// round 9
// speedup vs baseline: 1.4329x; 1.1701x over previous
#include <cuda_runtime.h>
#include <cuda_bf16.h>
#include <math.h>
#include <stdint.h>

// ===========================================================================
// Static scratch. Branch 0 = q (B=4096 rows), branch 1 = k (N=8192 rows).
// Per-branch arrays are [2][1024] flattened.
// ===========================================================================
__device__ float g_sum[2048];
__device__ float g_sumsq[2048];
__device__ float g_a[2048];
__device__ float g_dd[2048];
__device__ float g_bias2[2048];
__device__ float g_k2[8192];
__device__ __nv_bfloat16 g_Q1h[4096 * 1024], g_Q1l[4096 * 1024];
__device__ __nv_bfloat16 g_Q2h[4096 * 1024], g_Q2l[4096 * 1024];
__device__ __nv_bfloat16 g_P1h[8192 * 1024], g_P1l[8192 * 1024];
__device__ __nv_bfloat16 g_P2h[8192 * 1024], g_P2l[8192 * 1024];
__device__ __nv_bfloat16 g_WT0h[1024 * 1024], g_WT0l[1024 * 1024];
__device__ __nv_bfloat16 g_WT1h[1024 * 1024], g_WT1l[1024 * 1024];
__device__ __nv_bfloat16 g_qh[4096 * 256], g_ql[4096 * 256];
__device__ __nv_bfloat16 g_kh[8192 * 256], g_kl[8192 * 256];
__device__ float g_pm[4096 * 64], g_pl[4096 * 64], g_pw[4096 * 64];

// ===========================================================================
// Prep kernels (per-branch; br selects the [2]-indexed state)
// ===========================================================================
__global__ void zero_all() {
    int i = blockIdx.x * blockDim.x + threadIdx.x;
    if (i < 2048) { g_sum[i] = 0.f; g_sumsq[i] = 0.f; }
    if (i < 8192) g_k2[i] = 0.f;
}

__global__ void split_stats_b(const float* __restrict__ X,
                              __nv_bfloat16* __restrict__ hi,
                              __nv_bfloat16* __restrict__ lo,
                              int R, int Din, int br) {
    int c = blockIdx.x * blockDim.x + threadIdx.x;
    if (c >= Din) return;
    int chunk = R / gridDim.y;
    int r0 = blockIdx.y * chunk;
    float s = 0.f, s2 = 0.f;
    for (int r = r0; r < r0 + chunk; ++r) {
        size_t i = (size_t)r * Din + c;
        float v = X[i];
        __nv_bfloat16 h = __float2bfloat16(v);
        hi[i] = h;
        lo[i] = __float2bfloat16(v - __bfloat162float(h));
        s += v;
        s2 = fmaf(v, v, s2);
    }
    atomicAdd(&g_sum[br * 1024 + c], s);
    atomicAdd(&g_sumsq[br * 1024 + c], s2);
}

__global__ void finalize_bias_b(int R, int Din, int Dout,
                                const float* __restrict__ gam,
                                const float* __restrict__ bet,
                                const float* __restrict__ b, int br) {
    int off = br * 1024;
    int c = blockIdx.x * blockDim.x + threadIdx.x;
    if (c < Din) {
        float inv = 1.0f / (float)R;
        float mean = g_sum[off + c] * inv;
        float var = g_sumsq[off + c] * inv - mean * mean;
        float a = gam[c] * rsqrtf(var + 1e-5f);
        g_a[off + c] = a;
        g_dd[off + c] = bet[c] - mean * a;
    }
    if (c < Dout) {
        g_bias2[off + c] = b[c];
        g_sum[off + c] = 0.f;
        g_sumsq[off + c] = 0.f;
    }
}

__global__ void wprep_bias_b(const float* __restrict__ W, int Din, int Dout,
                             __nv_bfloat16* __restrict__ WTh,
                             __nv_bfloat16* __restrict__ WTl, int br) {
    __shared__ float tile[32][33];
    __shared__ float sbias[8][32];
    int off = br * 1024;
    int k0 = blockIdx.y * 32, n0 = blockIdx.x * 32;
    int tx = threadIdx.x, ty = threadIdx.y;
    float bp = 0.f;
    for (int i = ty; i < 32; i += 8) {
        float w = W[(size_t)(k0 + i) * Dout + n0 + tx];
        tile[i][tx] = g_a[off + k0 + i] * w;
        bp = fmaf(g_dd[off + k0 + i], w, bp);
    }
    sbias[ty][tx] = bp;
    __syncthreads();
    if (ty == 0) {
        float s = 0.f;
#pragma unroll
        for (int j = 0; j < 8; ++j) s += sbias[j][tx];
        atomicAdd(&g_bias2[off + n0 + tx], s);
    }
    for (int i = ty; i < 32; i += 8) {
        float v = tile[tx][i];
        size_t idx = (size_t)(n0 + i) * Din + (k0 + tx);
        __nv_bfloat16 h = __float2bfloat16(v);
        WTh[idx] = h;
        WTl[idx] = __float2bfloat16(v - __bfloat162float(h));
    }
}

// ===========================================================================
// GEMM machinery (R7 config): CTA 128x128, K-tile 32, 2-stage cp.async,
// 8 warps (2x4), warp tile 64x32, scalar LDS, 256 thr, 2 CTA/SM,
// 3-product bf16 emulation.
// ===========================================================================
#define LDKB 80
#define TILE_B (128 * LDKB)
#define STAGE_B (4 * TILE_B)
#define GEMM_SMEM (2 * STAGE_B)

__device__ __forceinline__ void mma_bf16(float* d, const uint32_t* a, const uint32_t* b) {
    asm volatile("mma.sync.aligned.m16n8k16.row.col.f32.bf16.bf16.f32 "
        "{%0,%1,%2,%3}, {%4,%5,%6,%7}, {%8,%9}, {%0,%1,%2,%3};"
        : "+f"(d[0]), "+f"(d[1]), "+f"(d[2]), "+f"(d[3])
        : "r"(a[0]), "r"(a[1]), "r"(a[2]), "r"(a[3]), "r"(b[0]), "r"(b[1]));
}

#define FILL_TILE(t, s)                                                        \
    do {                                                                       \
        char* base_ = smem + (s) * STAGE_B;                                    \
        const int k0_ = (t) << 5;                                              \
        _Pragma("unroll")                                                      \
        for (int l_ = 0; l_ < 8; ++l_) {                                       \
            int id_ = tid + (l_ << 8);                                         \
            int which_ = id_ >> 9;                                             \
            int e_ = id_ & 511;                                                \
            int row_ = e_ >> 2, c4_ = e_ & 3;                                  \
            const __nv_bfloat16* src_ =                                        \
                (which_ == 0) ? Ah : (which_ == 1) ? Al : (which_ == 2) ? Bh : Bl; \
            int grow_ = ((which_ < 2) ? m0 : n0) + row_;                       \
            const char* gp_ = (const char*)(src_ + (size_t)grow_ * K + k0_) + (c4_ << 4); \
            uint32_t sp_ = (uint32_t)__cvta_generic_to_shared(                 \
                base_ + which_ * TILE_B + row_ * LDKB + (c4_ << 4));           \
            asm volatile("cp.async.cg.shared.global [%0], [%1], 16;" :: "r"(sp_), "l"(gp_)); \
        }                                                                      \
        asm volatile("cp.async.commit_group;");                                \
    } while (0)

#define MMA_MAINLOOP()                                                         \
    do {                                                                       \
        FILL_TILE(0, 0);                                                       \
        for (int t = 0; t < T; ++t) {                                          \
            if (t + 1 < T) {                                                   \
                FILL_TILE(t + 1, (t + 1) & 1);                                 \
                asm volatile("cp.async.wait_group 1;");                        \
            } else {                                                           \
                asm volatile("cp.async.wait_group 0;");                        \
            }                                                                  \
            __syncthreads();                                                   \
            const char* st_ = smem + (t & 1) * STAGE_B;                        \
            _Pragma("unroll")                                                  \
            for (int kk = 0; kk < 2; ++kk) {                                   \
                const int kb_ = (kk << 4) + cc;                                \
                uint32_t bh_[4][2], bl_[4][2];                                 \
                _Pragma("unroll")                                              \
                for (int nt = 0; nt < 4; ++nt) {                               \
                    const char* pB_ = st_ + 2 * TILE_B + (wn * 32 + nt * 8 + g) * LDKB + kb_ * 2; \
                    bh_[nt][0] = *(const uint32_t*)pB_;                        \
                    bh_[nt][1] = *(const uint32_t*)(pB_ + 16);                 \
                    bl_[nt][0] = *(const uint32_t*)(pB_ + TILE_B);             \
                    bl_[nt][1] = *(const uint32_t*)(pB_ + TILE_B + 16);        \
                }                                                              \
                _Pragma("unroll")                                              \
                for (int mt = 0; mt < 4; ++mt) {                               \
                    const char* pA_ = st_ + (wm * 64 + mt * 16 + g) * LDKB + kb_ * 2; \
                    uint32_t ah_[4], al_[4];                                   \
                    ah_[0] = *(const uint32_t*)pA_;                            \
                    ah_[1] = *(const uint32_t*)(pA_ + 8 * LDKB);               \
                    ah_[2] = *(const uint32_t*)(pA_ + 16);                     \
                    ah_[3] = *(const uint32_t*)(pA_ + 8 * LDKB + 16);          \
                    al_[0] = *(const uint32_t*)(pA_ + TILE_B);                 \
                    al_[1] = *(const uint32_t*)(pA_ + TILE_B + 8 * LDKB);      \
                    al_[2] = *(const uint32_t*)(pA_ + TILE_B + 16);            \
                    al_[3] = *(const uint32_t*)(pA_ + TILE_B + 8 * LDKB + 16); \
                    _Pragma("unroll")                                          \
                    for (int nt = 0; nt < 4; ++nt) {                           \
                        mma_bf16(acc[mt][nt], ah_, bh_[nt]);                   \
                        mma_bf16(acc[mt][nt], ah_, bl_[nt]);                   \
                        mma_bf16(acc[mt][nt], al_, bh_[nt]);                   \
                    }                                                          \
                }                                                              \
            }                                                                  \
            __syncthreads();                                                   \
        }                                                                      \
    } while (0)

#define GEMM_THREAD_IDS()                                                      \
    const int tid = threadIdx.x;                                               \
    const int wid = tid >> 5, lane = tid & 31;                                 \
    const int g = lane >> 2;                                                   \
    const int cc = (lane & 3) * 2;                                             \
    const int wm = wid >> 2, wn = wid & 3;                                     \
    float acc[4][4][4];                                                        \
    _Pragma("unroll")                                                          \
    for (int i = 0; i < 4; ++i)                                                \
        _Pragma("unroll")                                                      \
        for (int j = 0; j < 4; ++j)                                            \
            _Pragma("unroll")                                                  \
            for (int r = 0; r < 4; ++r) acc[i][j][r] = 0.f;

// ===========================================================================
// Trunk GEMM (single branch, br indexes bias/stat arrays).
// accum 1: column stats of tanh -> g_sum/g_sumsq[br]; accum 2: row sumsq -> g_k2
// ===========================================================================
__global__ __launch_bounds__(256, 2) void gemm_trunk(
    const __nv_bfloat16* __restrict__ Ah, const __nv_bfloat16* __restrict__ Al,
    const __nv_bfloat16* __restrict__ Bh, const __nv_bfloat16* __restrict__ Bl,
    int K, int ldOut, int accum, int br,
    __nv_bfloat16* __restrict__ Yh, __nv_bfloat16* __restrict__ Yl)
{
    extern __shared__ __align__(16) char smem[];
    GEMM_THREAD_IDS();
    const int m0 = blockIdx.y * 128, n0 = blockIdx.x * 128;
    const int T = K >> 5;
    const float* bias = g_bias2 + br * 1024;

    MMA_MAINLOOP();

    float* s_sum = (float*)smem;
    float* s_sq  = (float*)smem + 128;
    if (accum) {
        if (tid < 128) { s_sum[tid] = 0.f; s_sq[tid] = 0.f; }
        __syncthreads();
    }

#pragma unroll
    for (int mt = 0; mt < 4; ++mt) {
#pragma unroll
        for (int nt = 0; nt < 4; ++nt) {
            int row = m0 + wm * 64 + mt * 16 + g;
            int col = n0 + wn * 32 + nt * 8 + cc;
            float* a = acc[mt][nt];
            float bA = bias[col], bB = bias[col + 1];
#pragma unroll
            for (int h = 0; h < 2; ++h) {
                int r = row + h * 8;
                float v0 = tanhf(a[h * 2 + 0] + bA);
                float v1 = tanhf(a[h * 2 + 1] + bB);
                a[h * 2 + 0] = v0;
                a[h * 2 + 1] = v1;
                __nv_bfloat162 hp, lp;
                hp.x = __float2bfloat16(v0);
                hp.y = __float2bfloat16(v1);
                lp.x = __float2bfloat16(v0 - __bfloat162float(hp.x));
                lp.y = __float2bfloat16(v1 - __bfloat162float(hp.y));
                *(uint32_t*)(Yh + (size_t)r * ldOut + col) = *(uint32_t*)&hp;
                *(uint32_t*)(Yl + (size_t)r * ldOut + col) = *(uint32_t*)&lp;
            }
        }
    }

    if (accum == 1) {
#pragma unroll
        for (int nt = 0; nt < 4; ++nt) {
            int lc = wn * 32 + nt * 8 + cc;
            float s0 = 0.f, q0 = 0.f, s1 = 0.f, q1 = 0.f;
#pragma unroll
            for (int mt = 0; mt < 4; ++mt) {
                float* a = acc[mt][nt];
#pragma unroll
                for (int h = 0; h < 2; ++h) {
                    s0 += a[h * 2 + 0]; q0 = fmaf(a[h * 2 + 0], a[h * 2 + 0], q0);
                    s1 += a[h * 2 + 1]; q1 = fmaf(a[h * 2 + 1], a[h * 2 + 1], q1);
                }
            }
            atomicAdd(&s_sum[lc], s0);     atomicAdd(&s_sq[lc], q0);
            atomicAdd(&s_sum[lc + 1], s1); atomicAdd(&s_sq[lc + 1], q1);
        }
        __syncthreads();
        if (tid < 128) {
            atomicAdd(&g_sum[br * 1024 + n0 + tid], s_sum[tid]);
            atomicAdd(&g_sumsq[br * 1024 + n0 + tid], s_sq[tid]);
        }
    } else if (accum == 2) {
#pragma unroll
        for (int mt = 0; mt < 4; ++mt) {
#pragma unroll
            for (int h = 0; h < 2; ++h) {
                int lr = wm * 64 + mt * 16 + h * 8 + g;
                float s = 0.f;
#pragma unroll
                for (int nt = 0; nt < 4; ++nt) {
                    float v0 = acc[mt][nt][h * 2 + 0];
                    float v1 = acc[mt][nt][h * 2 + 1];
                    s = fmaf(v0, v0, s);
                    s = fmaf(v1, v1, s);
                }
                atomicAdd(&s_sum[lr], s);
            }
        }
        __syncthreads();
        if (tid < 128) atomicAdd(&g_k2[m0 + tid], s_sum[tid]);
    }
}

// ===========================================================================
// Flash sim+softmax (unchanged)
// ===========================================================================
__global__ __launch_bounds__(256, 2) void sim_flash(
    const __nv_bfloat16* __restrict__ Ah, const __nv_bfloat16* __restrict__ Al,
    const __nv_bfloat16* __restrict__ Bh, const __nv_bfloat16* __restrict__ Bl,
    const float* __restrict__ y, int K, int nsplit)
{
    extern __shared__ __align__(16) char smem[];
    GEMM_THREAD_IDS();
    const int m0 = blockIdx.y * 128, n0 = blockIdx.x * 128;
    const int T = K >> 5;
    MMA_MAINLOOP();

    float yv[4][2], k2v[4][2];
#pragma unroll
    for (int nt = 0; nt < 4; ++nt) {
        int col = n0 + wn * 32 + nt * 8 + cc;
        yv[nt][0] = y[col];     yv[nt][1] = y[col + 1];
        k2v[nt][0] = g_k2[col]; k2v[nt][1] = g_k2[col + 1];
    }

    float* red = (float*)smem;
#pragma unroll
    for (int mt = 0; mt < 4; ++mt) {
#pragma unroll
        for (int h = 0; h < 2; ++h) {
            float lg[4][2];
            float mx = -3.4e38f;
#pragma unroll
            for (int nt = 0; nt < 4; ++nt) {
#pragma unroll
                for (int c2 = 0; c2 < 2; ++c2) {
                    float v = 2.f * acc[mt][nt][h * 2 + c2] - k2v[nt][c2];
                    lg[nt][c2] = v;
                    mx = fmaxf(mx, v);
                }
            }
            mx = fmaxf(mx, __shfl_xor_sync(0xFFFFFFFF, mx, 1));
            mx = fmaxf(mx, __shfl_xor_sync(0xFFFFFFFF, mx, 2));
            float s = 0.f, w = 0.f;
#pragma unroll
            for (int nt = 0; nt < 4; ++nt) {
#pragma unroll
                for (int c2 = 0; c2 < 2; ++c2) {
                    float e = __expf(lg[nt][c2] - mx);
                    s += e;
                    w = fmaf(e, yv[nt][c2], w);
                }
            }
            s += __shfl_xor_sync(0xFFFFFFFF, s, 1);
            s += __shfl_xor_sync(0xFFFFFFFF, s, 2);
            w += __shfl_xor_sync(0xFFFFFFFF, w, 1);
            w += __shfl_xor_sync(0xFFFFFFFF, w, 2);
            if ((lane & 3) == 0) {
                int lr = wm * 64 + mt * 16 + h * 8 + g;
                red[(lr * 4 + wn) * 3 + 0] = mx;
                red[(lr * 4 + wn) * 3 + 1] = s;
                red[(lr * 4 + wn) * 3 + 2] = w;
            }
        }
    }
    __syncthreads();
    if (tid < 128) {
        float M = -3.4e38f;
#pragma unroll
        for (int j = 0; j < 4; ++j) M = fmaxf(M, red[(tid * 4 + j) * 3 + 0]);
        float L = 0.f, W = 0.f;
#pragma unroll
        for (int j = 0; j < 4; ++j) {
            float e = __expf(red[(tid * 4 + j) * 3 + 0] - M);
            L = fmaf(red[(tid * 4 + j) * 3 + 1], e, L);
            W = fmaf(red[(tid * 4 + j) * 3 + 2], e, W);
        }
        size_t idx = (size_t)(m0 + tid) * nsplit + blockIdx.x;
        g_pm[idx] = M;
        g_pl[idx] = L;
        g_pw[idx] = W;
    }
}

__global__ void combine_out(float* __restrict__ out, int S) {
    int row = blockIdx.x * 8 + (threadIdx.x >> 5);
    int lane = threadIdx.x & 31;
    size_t base = (size_t)row * S;
    float m1 = g_pm[base + lane], m2 = g_pm[base + lane + 32];
    float l1 = g_pl[base + lane], l2 = g_pl[base + lane + 32];
    float w1 = g_pw[base + lane], w2 = g_pw[base + lane + 32];
    float M = fmaxf(m1, m2);
#pragma unroll
    for (int o = 16; o > 0; o >>= 1)
        M = fmaxf(M, __shfl_xor_sync(0xFFFFFFFF, M, o));
    float L = l1 * __expf(m1 - M) + l2 * __expf(m2 - M);
    float W = w1 * __expf(m1 - M) + w2 * __expf(m2 - M);
#pragma unroll
    for (int o = 16; o > 0; o >>= 1) {
        L += __shfl_xor_sync(0xFFFFFFFF, L, o);
        W += __shfl_xor_sync(0xFFFFFFFF, W, o);
    }
    if (lane == 0) {
        float r = W / L;
        out[row] = fminf(fmaxf(r, 0.f), 1.f);
    }
}

// ===========================================================================
// Host launcher — fork/join two streams (q on capture stream, k on s2)
// ===========================================================================
extern "C" void kernel_launch(void* const* d_in, const int* in_sizes, int n_in,
                              void* d_out, int out_size)
{
    const float* x   = (const float*)d_in[0];
    const float* xn  = (const float*)d_in[1];
    const float* y   = (const float*)d_in[2];
    const float* Ws[3] = {(const float*)d_in[3], (const float*)d_in[7], (const float*)d_in[11]};
    const float* bs[3] = {(const float*)d_in[4], (const float*)d_in[8], (const float*)d_in[12]};
    const float* gs[3] = {(const float*)d_in[5], (const float*)d_in[9], (const float*)d_in[13]};
    const float* es[3] = {(const float*)d_in[6], (const float*)d_in[10], (const float*)d_in[14]};

    const int D  = in_sizes[5];
    const int B  = in_sizes[0] / D;      // 4096
    const int N  = in_sizes[2];          // 8192
    const int dims[4] = {D, in_sizes[4], in_sizes[8], in_sizes[12]};

    __nv_bfloat16 *q1h, *q1l, *q2h, *q2l, *p1h, *p1l, *p2h, *p2l;
    __nv_bfloat16 *w0h, *w0l, *w1h, *w1l, *qh, *ql, *kh, *kl;
    cudaGetSymbolAddress((void**)&q1h, g_Q1h); cudaGetSymbolAddress((void**)&q1l, g_Q1l);
    cudaGetSymbolAddress((void**)&q2h, g_Q2h); cudaGetSymbolAddress((void**)&q2l, g_Q2l);
    cudaGetSymbolAddress((void**)&p1h, g_P1h); cudaGetSymbolAddress((void**)&p1l, g_P1l);
    cudaGetSymbolAddress((void**)&p2h, g_P2h); cudaGetSymbolAddress((void**)&p2l, g_P2l);
    cudaGetSymbolAddress((void**)&w0h, g_WT0h); cudaGetSymbolAddress((void**)&w0l, g_WT0l);
    cudaGetSymbolAddress((void**)&w1h, g_WT1h); cudaGetSymbolAddress((void**)&w1l, g_WT1l);
    cudaGetSymbolAddress((void**)&qh, g_qh);   cudaGetSymbolAddress((void**)&ql, g_ql);
    cudaGetSymbolAddress((void**)&kh, g_kh);   cudaGetSymbolAddress((void**)&kl, g_kl);

    cudaFuncSetAttribute(gemm_trunk, cudaFuncAttributeMaxDynamicSharedMemorySize, GEMM_SMEM);
    cudaFuncSetAttribute(sim_flash, cudaFuncAttributeMaxDynamicSharedMemorySize, GEMM_SMEM);

    // one-time stream/event creation (resources only; no device memory)
    static cudaStream_t s2 = nullptr;
    static cudaEvent_t evFork = nullptr, evJoin = nullptr;
    if (s2 == nullptr) {
        cudaStreamCreateWithFlags(&s2, cudaStreamNonBlocking);
        cudaEventCreateWithFlags(&evFork, cudaEventDisableTiming);
        cudaEventCreateWithFlags(&evJoin, cudaEventDisableTiming);
    }

    zero_all<<<32, 256>>>();
    cudaEventRecord(evFork, 0);
    cudaStreamWaitEvent(s2, evFork, 0);

    // ---- q branch on default stream, k branch on s2 ----
    split_stats_b<<<dim3(D / 256, 64), 256>>>(x, q1h, q1l, B, D, 0);
    split_stats_b<<<dim3(D / 256, 64), 256, 0, s2>>>(xn, p1h, p1l, N, D, 1);

    __nv_bfloat16 *qa_h = q1h, *qa_l = q1l, *qb_h = q2h, *qb_l = q2l;
    __nv_bfloat16 *ka_h = p1h, *ka_l = p1l, *kb_h = p2h, *kb_l = p2l;

    for (int i = 0; i < 3; ++i) {
        int Din = dims[i], Dout = dims[i + 1];
        int mx = Din > Dout ? Din : Dout;
        int nx = Dout / 128;
        int accum_mid = (i < 2) ? 1 : 0;

        // q branch (default stream)
        finalize_bias_b<<<(mx + 255) / 256, 256>>>(B, Din, Dout, gs[i], es[i], bs[i], 0);
        wprep_bias_b<<<dim3(Dout / 32, Din / 32), dim3(32, 8)>>>(Ws[i], Din, Dout, w0h, w0l, 0);
        __nv_bfloat16* yq_h = (i == 2) ? qh : qb_h;
        __nv_bfloat16* yq_l = (i == 2) ? ql : qb_l;
        gemm_trunk<<<dim3(nx, B / 128), 256, GEMM_SMEM>>>(
            qa_h, qa_l, w0h, w0l, Din, Dout, accum_mid, 0, yq_h, yq_l);

        // k branch (s2)
        finalize_bias_b<<<(mx + 255) / 256, 256, 0, s2>>>(N, Din, Dout, gs[i], es[i], bs[i], 1);
        wprep_bias_b<<<dim3(Dout / 32, Din / 32), dim3(32, 8), 0, s2>>>(Ws[i], Din, Dout, w1h, w1l, 1);
        __nv_bfloat16* yk_h = (i == 2) ? kh : kb_h;
        __nv_bfloat16* yk_l = (i == 2) ? kl : kb_l;
        int accum_k = (i < 2) ? 1 : 2;
        gemm_trunk<<<dim3(nx, N / 128), 256, GEMM_SMEM, s2>>>(
            ka_h, ka_l, w1h, w1l, Din, Dout, accum_k, 1, yk_h, yk_l);

        __nv_bfloat16* t;
        t = qa_h; qa_h = qb_h; qb_h = t;  t = qa_l; qa_l = qb_l; qb_l = t;
        t = ka_h; ka_h = kb_h; kb_h = t;  t = ka_l; ka_l = kb_l; kb_l = t;
    }

    // join: default stream waits for k branch
    cudaEventRecord(evJoin, s2);
    cudaStreamWaitEvent(0, evJoin, 0);

    const int NSPLIT = N / 128;
    sim_flash<<<dim3(NSPLIT, B / 128), 256, GEMM_SMEM>>>(
        qh, ql, kh, kl, y, dims[3], NSPLIT);
    combine_out<<<B / 8, 256>>>((float*)d_out, NSPLIT);
}

// round 10
// speedup vs baseline: 1.4378x; 1.0034x over previous
#include <cuda_runtime.h>
#include <cuda_bf16.h>
#include <math.h>
#include <stdint.h>

// ===========================================================================
// Static scratch. Branch 0 = q (B=4096 rows), branch 1 = k (N=8192 rows).
// Stats: [branch][layer-slot 0..3][1024]; slot 0 = raw input stats,
// slot i+1 = stats of layer-i output. Bias: [branch][layer 0..2][1024].
// All pre-zeroed once by zero_all.
// ===========================================================================
__device__ float g_sum[2 * 4 * 1024];
__device__ float g_sumsq[2 * 4 * 1024];
__device__ float g_bias2[2 * 3 * 1024];
__device__ float g_k2[8192];
__device__ __nv_bfloat16 g_Q1h[4096 * 1024], g_Q1l[4096 * 1024];
__device__ __nv_bfloat16 g_Q2h[4096 * 1024], g_Q2l[4096 * 1024];
__device__ __nv_bfloat16 g_P1h[8192 * 1024], g_P1l[8192 * 1024];
__device__ __nv_bfloat16 g_P2h[8192 * 1024], g_P2l[8192 * 1024];
__device__ __nv_bfloat16 g_WT0h[1024 * 1024], g_WT0l[1024 * 1024];
__device__ __nv_bfloat16 g_WT1h[1024 * 1024], g_WT1l[1024 * 1024];
__device__ __nv_bfloat16 g_qh[4096 * 256], g_ql[4096 * 256];
__device__ __nv_bfloat16 g_kh[8192 * 256], g_kl[8192 * 256];
__device__ float g_pm[4096 * 64], g_pl[4096 * 64], g_pw[4096 * 64];

// ===========================================================================
// Prep kernels
// ===========================================================================
__global__ void zero_all() {
    int i = blockIdx.x * blockDim.x + threadIdx.x;   // 0..8191
    g_sum[i] = 0.f;
    g_sumsq[i] = 0.f;
    g_k2[i] = 0.f;
    if (i < 6144) g_bias2[i] = 0.f;
}

__global__ void split_stats_b(const float* __restrict__ X,
                              __nv_bfloat16* __restrict__ hi,
                              __nv_bfloat16* __restrict__ lo,
                              int R, int Din, int br) {
    int c = blockIdx.x * blockDim.x + threadIdx.x;
    if (c >= Din) return;
    int chunk = R / gridDim.y;
    int r0 = blockIdx.y * chunk;
    float s = 0.f, s2 = 0.f;
    for (int r = r0; r < r0 + chunk; ++r) {
        size_t i = (size_t)r * Din + c;
        float v = X[i];
        __nv_bfloat16 h = __float2bfloat16(v);
        hi[i] = h;
        lo[i] = __float2bfloat16(v - __bfloat162float(h));
        s += v;
        s2 = fmaf(v, v, s2);
    }
    atomicAdd(&g_sum[br * 4096 + c], s);     // slot 0
    atomicAdd(&g_sumsq[br * 4096 + c], s2);
}

// Fused: BN finalize (per-block, 32 k-cols) + WT transpose/scale/split +
// bias2 accumulation into per-(branch,layer) slot.
__global__ void wprep_fused(const float* __restrict__ W, int Din, int Dout,
                            __nv_bfloat16* __restrict__ WTh,
                            __nv_bfloat16* __restrict__ WTl,
                            int br, int layer, int R,
                            const float* __restrict__ gam,
                            const float* __restrict__ bet) {
    __shared__ float tile[32][33];
    __shared__ float sbias[8][32];
    __shared__ float sa[32], sdd[32];
    int k0 = blockIdx.y * 32, n0 = blockIdx.x * 32;
    int tx = threadIdx.x, ty = threadIdx.y;

    if (ty == 0) {
        int c = k0 + tx;
        int offs = (br * 4 + layer) * 1024;
        float inv = 1.0f / (float)R;
        float mean = g_sum[offs + c] * inv;
        float var = g_sumsq[offs + c] * inv - mean * mean;
        float a = gam[c] * rsqrtf(var + 1e-5f);
        sa[tx] = a;
        sdd[tx] = bet[c] - mean * a;
    }
    __syncthreads();

    float bp = 0.f;
    for (int i = ty; i < 32; i += 8) {
        float w = W[(size_t)(k0 + i) * Dout + n0 + tx];
        tile[i][tx] = sa[i] * w;
        bp = fmaf(sdd[i], w, bp);
    }
    sbias[ty][tx] = bp;
    __syncthreads();
    if (ty == 0) {
        float s = 0.f;
#pragma unroll
        for (int j = 0; j < 8; ++j) s += sbias[j][tx];
        atomicAdd(&g_bias2[(br * 3 + layer) * 1024 + n0 + tx], s);
    }
    for (int i = ty; i < 32; i += 8) {
        float v = tile[tx][i];
        size_t idx = (size_t)(n0 + i) * Din + (k0 + tx);
        __nv_bfloat16 h = __float2bfloat16(v);
        WTh[idx] = h;
        WTl[idx] = __float2bfloat16(v - __bfloat162float(h));
    }
}

// ===========================================================================
// GEMM machinery (R7 config): CTA 128x128, K-tile 32, 2-stage cp.async,
// 8 warps (2x4), warp tile 64x32, scalar LDS, 256 thr, 2 CTA/SM,
// 3-product bf16 emulation.
// ===========================================================================
#define LDKB 80
#define TILE_B (128 * LDKB)
#define STAGE_B (4 * TILE_B)
#define GEMM_SMEM (2 * STAGE_B)

__device__ __forceinline__ void mma_bf16(float* d, const uint32_t* a, const uint32_t* b) {
    asm volatile("mma.sync.aligned.m16n8k16.row.col.f32.bf16.bf16.f32 "
        "{%0,%1,%2,%3}, {%4,%5,%6,%7}, {%8,%9}, {%0,%1,%2,%3};"
        : "+f"(d[0]), "+f"(d[1]), "+f"(d[2]), "+f"(d[3])
        : "r"(a[0]), "r"(a[1]), "r"(a[2]), "r"(a[3]), "r"(b[0]), "r"(b[1]));
}

#define FILL_TILE(t, s)                                                        \
    do {                                                                       \
        char* base_ = smem + (s) * STAGE_B;                                    \
        const int k0_ = (t) << 5;                                              \
        _Pragma("unroll")                                                      \
        for (int l_ = 0; l_ < 8; ++l_) {                                       \
            int id_ = tid + (l_ << 8);                                         \
            int which_ = id_ >> 9;                                             \
            int e_ = id_ & 511;                                                \
            int row_ = e_ >> 2, c4_ = e_ & 3;                                  \
            const __nv_bfloat16* src_ =                                        \
                (which_ == 0) ? Ah : (which_ == 1) ? Al : (which_ == 2) ? Bh : Bl; \
            int grow_ = ((which_ < 2) ? m0 : n0) + row_;                       \
            const char* gp_ = (const char*)(src_ + (size_t)grow_ * K + k0_) + (c4_ << 4); \
            uint32_t sp_ = (uint32_t)__cvta_generic_to_shared(                 \
                base_ + which_ * TILE_B + row_ * LDKB + (c4_ << 4));           \
            asm volatile("cp.async.cg.shared.global [%0], [%1], 16;" :: "r"(sp_), "l"(gp_)); \
        }                                                                      \
        asm volatile("cp.async.commit_group;");                                \
    } while (0)

#define MMA_MAINLOOP()                                                         \
    do {                                                                       \
        FILL_TILE(0, 0);                                                       \
        for (int t = 0; t < T; ++t) {                                          \
            if (t + 1 < T) {                                                   \
                FILL_TILE(t + 1, (t + 1) & 1);                                 \
                asm volatile("cp.async.wait_group 1;");                        \
            } else {                                                           \
                asm volatile("cp.async.wait_group 0;");                        \
            }                                                                  \
            __syncthreads();                                                   \
            const char* st_ = smem + (t & 1) * STAGE_B;                        \
            _Pragma("unroll")                                                  \
            for (int kk = 0; kk < 2; ++kk) {                                   \
                const int kb_ = (kk << 4) + cc;                                \
                uint32_t bh_[4][2], bl_[4][2];                                 \
                _Pragma("unroll")                                              \
                for (int nt = 0; nt < 4; ++nt) {                               \
                    const char* pB_ = st_ + 2 * TILE_B + (wn * 32 + nt * 8 + g) * LDKB + kb_ * 2; \
                    bh_[nt][0] = *(const uint32_t*)pB_;                        \
                    bh_[nt][1] = *(const uint32_t*)(pB_ + 16);                 \
                    bl_[nt][0] = *(const uint32_t*)(pB_ + TILE_B);             \
                    bl_[nt][1] = *(const uint32_t*)(pB_ + TILE_B + 16);        \
                }                                                              \
                _Pragma("unroll")                                              \
                for (int mt = 0; mt < 4; ++mt) {                               \
                    const char* pA_ = st_ + (wm * 64 + mt * 16 + g) * LDKB + kb_ * 2; \
                    uint32_t ah_[4], al_[4];                                   \
                    ah_[0] = *(const uint32_t*)pA_;                            \
                    ah_[1] = *(const uint32_t*)(pA_ + 8 * LDKB);               \
                    ah_[2] = *(const uint32_t*)(pA_ + 16);                     \
                    ah_[3] = *(const uint32_t*)(pA_ + 8 * LDKB + 16);          \
                    al_[0] = *(const uint32_t*)(pA_ + TILE_B);                 \
                    al_[1] = *(const uint32_t*)(pA_ + TILE_B + 8 * LDKB);      \
                    al_[2] = *(const uint32_t*)(pA_ + TILE_B + 16);            \
                    al_[3] = *(const uint32_t*)(pA_ + TILE_B + 8 * LDKB + 16); \
                    _Pragma("unroll")                                          \
                    for (int nt = 0; nt < 4; ++nt) {                           \
                        mma_bf16(acc[mt][nt], ah_, bh_[nt]);                   \
                        mma_bf16(acc[mt][nt], ah_, bl_[nt]);                   \
                        mma_bf16(acc[mt][nt], al_, bh_[nt]);                   \
                    }                                                          \
                }                                                              \
            }                                                                  \
            __syncthreads();                                                   \
        }                                                                      \
    } while (0)

#define GEMM_THREAD_IDS()                                                      \
    const int tid = threadIdx.x;                                               \
    const int wid = tid >> 5, lane = tid & 31;                                 \
    const int g = lane >> 2;                                                   \
    const int cc = (lane & 3) * 2;                                             \
    const int wm = wid >> 2, wn = wid & 3;                                     \
    float acc[4][4][4];                                                        \
    _Pragma("unroll")                                                          \
    for (int i = 0; i < 4; ++i)                                                \
        _Pragma("unroll")                                                      \
        for (int j = 0; j < 4; ++j)                                            \
            _Pragma("unroll")                                                  \
            for (int r = 0; r < 4; ++r) acc[i][j][r] = 0.f;

// ===========================================================================
// Trunk GEMM. bias = g_bias2[br][layer] + bvec. accum 1: col stats of tanh
// -> g_sum/g_sumsq slot layer+1; accum 2: row sumsq -> g_k2.
// ===========================================================================
__global__ __launch_bounds__(256, 2) void gemm_trunk(
    const __nv_bfloat16* __restrict__ Ah, const __nv_bfloat16* __restrict__ Al,
    const __nv_bfloat16* __restrict__ Bh, const __nv_bfloat16* __restrict__ Bl,
    const float* __restrict__ bvec,
    int K, int ldOut, int accum, int br, int layer,
    __nv_bfloat16* __restrict__ Yh, __nv_bfloat16* __restrict__ Yl)
{
    extern __shared__ __align__(16) char smem[];
    GEMM_THREAD_IDS();
    const int m0 = blockIdx.y * 128, n0 = blockIdx.x * 128;
    const int T = K >> 5;
    const float* bias = g_bias2 + (br * 3 + layer) * 1024;

    MMA_MAINLOOP();

    float* s_sum = (float*)smem;
    float* s_sq  = (float*)smem + 128;
    if (accum) {
        if (tid < 128) { s_sum[tid] = 0.f; s_sq[tid] = 0.f; }
        __syncthreads();
    }

#pragma unroll
    for (int mt = 0; mt < 4; ++mt) {
#pragma unroll
        for (int nt = 0; nt < 4; ++nt) {
            int row = m0 + wm * 64 + mt * 16 + g;
            int col = n0 + wn * 32 + nt * 8 + cc;
            float* a = acc[mt][nt];
            float bA = bias[col] + bvec[col];
            float bB = bias[col + 1] + bvec[col + 1];
#pragma unroll
            for (int h = 0; h < 2; ++h) {
                int r = row + h * 8;
                float v0 = tanhf(a[h * 2 + 0] + bA);
                float v1 = tanhf(a[h * 2 + 1] + bB);
                a[h * 2 + 0] = v0;
                a[h * 2 + 1] = v1;
                __nv_bfloat162 hp, lp;
                hp.x = __float2bfloat16(v0);
                hp.y = __float2bfloat16(v1);
                lp.x = __float2bfloat16(v0 - __bfloat162float(hp.x));
                lp.y = __float2bfloat16(v1 - __bfloat162float(hp.y));
                *(uint32_t*)(Yh + (size_t)r * ldOut + col) = *(uint32_t*)&hp;
                *(uint32_t*)(Yl + (size_t)r * ldOut + col) = *(uint32_t*)&lp;
            }
        }
    }

    if (accum == 1) {
#pragma unroll
        for (int nt = 0; nt < 4; ++nt) {
            int lc = wn * 32 + nt * 8 + cc;
            float s0 = 0.f, q0 = 0.f, s1 = 0.f, q1 = 0.f;
#pragma unroll
            for (int mt = 0; mt < 4; ++mt) {
                float* a = acc[mt][nt];
#pragma unroll
                for (int h = 0; h < 2; ++h) {
                    s0 += a[h * 2 + 0]; q0 = fmaf(a[h * 2 + 0], a[h * 2 + 0], q0);
                    s1 += a[h * 2 + 1]; q1 = fmaf(a[h * 2 + 1], a[h * 2 + 1], q1);
                }
            }
            atomicAdd(&s_sum[lc], s0);     atomicAdd(&s_sq[lc], q0);
            atomicAdd(&s_sum[lc + 1], s1); atomicAdd(&s_sq[lc + 1], q1);
        }
        __syncthreads();
        if (tid < 128) {
            int offs = (br * 4 + layer + 1) * 1024 + n0 + tid;
            atomicAdd(&g_sum[offs], s_sum[tid]);
            atomicAdd(&g_sumsq[offs], s_sq[tid]);
        }
    } else if (accum == 2) {
#pragma unroll
        for (int mt = 0; mt < 4; ++mt) {
#pragma unroll
            for (int h = 0; h < 2; ++h) {
                int lr = wm * 64 + mt * 16 + h * 8 + g;
                float s = 0.f;
#pragma unroll
                for (int nt = 0; nt < 4; ++nt) {
                    float v0 = acc[mt][nt][h * 2 + 0];
                    float v1 = acc[mt][nt][h * 2 + 1];
                    s = fmaf(v0, v0, s);
                    s = fmaf(v1, v1, s);
                }
                atomicAdd(&s_sum[lr], s);
            }
        }
        __syncthreads();
        if (tid < 128) atomicAdd(&g_k2[m0 + tid], s_sum[tid]);
    }
}

// ===========================================================================
// Flash sim+softmax (unchanged)
// ===========================================================================
__global__ __launch_bounds__(256, 2) void sim_flash(
    const __nv_bfloat16* __restrict__ Ah, const __nv_bfloat16* __restrict__ Al,
    const __nv_bfloat16* __restrict__ Bh, const __nv_bfloat16* __restrict__ Bl,
    const float* __restrict__ y, int K, int nsplit)
{
    extern __shared__ __align__(16) char smem[];
    GEMM_THREAD_IDS();
    const int m0 = blockIdx.y * 128, n0 = blockIdx.x * 128;
    const int T = K >> 5;
    MMA_MAINLOOP();

    float yv[4][2], k2v[4][2];
#pragma unroll
    for (int nt = 0; nt < 4; ++nt) {
        int col = n0 + wn * 32 + nt * 8 + cc;
        yv[nt][0] = y[col];     yv[nt][1] = y[col + 1];
        k2v[nt][0] = g_k2[col]; k2v[nt][1] = g_k2[col + 1];
    }

    float* red = (float*)smem;
#pragma unroll
    for (int mt = 0; mt < 4; ++mt) {
#pragma unroll
        for (int h = 0; h < 2; ++h) {
            float lg[4][2];
            float mx = -3.4e38f;
#pragma unroll
            for (int nt = 0; nt < 4; ++nt) {
#pragma unroll
                for (int c2 = 0; c2 < 2; ++c2) {
                    float v = 2.f * acc[mt][nt][h * 2 + c2] - k2v[nt][c2];
                    lg[nt][c2] = v;
                    mx = fmaxf(mx, v);
                }
            }
            mx = fmaxf(mx, __shfl_xor_sync(0xFFFFFFFF, mx, 1));
            mx = fmaxf(mx, __shfl_xor_sync(0xFFFFFFFF, mx, 2));
            float s = 0.f, w = 0.f;
#pragma unroll
            for (int nt = 0; nt < 4; ++nt) {
#pragma unroll
                for (int c2 = 0; c2 < 2; ++c2) {
                    float e = __expf(lg[nt][c2] - mx);
                    s += e;
                    w = fmaf(e, yv[nt][c2], w);
                }
            }
            s += __shfl_xor_sync(0xFFFFFFFF, s, 1);
            s += __shfl_xor_sync(0xFFFFFFFF, s, 2);
            w += __shfl_xor_sync(0xFFFFFFFF, w, 1);
            w += __shfl_xor_sync(0xFFFFFFFF, w, 2);
            if ((lane & 3) == 0) {
                int lr = wm * 64 + mt * 16 + h * 8 + g;
                red[(lr * 4 + wn) * 3 + 0] = mx;
                red[(lr * 4 + wn) * 3 + 1] = s;
                red[(lr * 4 + wn) * 3 + 2] = w;
            }
        }
    }
    __syncthreads();
    if (tid < 128) {
        float M = -3.4e38f;
#pragma unroll
        for (int j = 0; j < 4; ++j) M = fmaxf(M, red[(tid * 4 + j) * 3 + 0]);
        float L = 0.f, W = 0.f;
#pragma unroll
        for (int j = 0; j < 4; ++j) {
            float e = __expf(red[(tid * 4 + j) * 3 + 0] - M);
            L = fmaf(red[(tid * 4 + j) * 3 + 1], e, L);
            W = fmaf(red[(tid * 4 + j) * 3 + 2], e, W);
        }
        size_t idx = (size_t)(m0 + tid) * nsplit + blockIdx.x;
        g_pm[idx] = M;
        g_pl[idx] = L;
        g_pw[idx] = W;
    }
}

__global__ void combine_out(float* __restrict__ out, int S) {
    int row = blockIdx.x * 8 + (threadIdx.x >> 5);
    int lane = threadIdx.x & 31;
    size_t base = (size_t)row * S;
    float m1 = g_pm[base + lane], m2 = g_pm[base + lane + 32];
    float l1 = g_pl[base + lane], l2 = g_pl[base + lane + 32];
    float w1 = g_pw[base + lane], w2 = g_pw[base + lane + 32];
    float M = fmaxf(m1, m2);
#pragma unroll
    for (int o = 16; o > 0; o >>= 1)
        M = fmaxf(M, __shfl_xor_sync(0xFFFFFFFF, M, o));
    float L = l1 * __expf(m1 - M) + l2 * __expf(m2 - M);
    float W = w1 * __expf(m1 - M) + w2 * __expf(m2 - M);
#pragma unroll
    for (int o = 16; o > 0; o >>= 1) {
        L += __shfl_xor_sync(0xFFFFFFFF, L, o);
        W += __shfl_xor_sync(0xFFFFFFFF, W, o);
    }
    if (lane == 0) {
        float r = W / L;
        out[row] = fminf(fmaxf(r, 0.f), 1.f);
    }
}

// ===========================================================================
// Host launcher — fork/join two streams (q on capture stream, k on s2)
// ===========================================================================
extern "C" void kernel_launch(void* const* d_in, const int* in_sizes, int n_in,
                              void* d_out, int out_size)
{
    const float* x   = (const float*)d_in[0];
    const float* xn  = (const float*)d_in[1];
    const float* y   = (const float*)d_in[2];
    const float* Ws[3] = {(const float*)d_in[3], (const float*)d_in[7], (const float*)d_in[11]};
    const float* bs[3] = {(const float*)d_in[4], (const float*)d_in[8], (const float*)d_in[12]};
    const float* gs[3] = {(const float*)d_in[5], (const float*)d_in[9], (const float*)d_in[13]};
    const float* es[3] = {(const float*)d_in[6], (const float*)d_in[10], (const float*)d_in[14]};

    const int D  = in_sizes[5];
    const int B  = in_sizes[0] / D;      // 4096
    const int N  = in_sizes[2];          // 8192
    const int dims[4] = {D, in_sizes[4], in_sizes[8], in_sizes[12]};

    __nv_bfloat16 *q1h, *q1l, *q2h, *q2l, *p1h, *p1l, *p2h, *p2l;
    __nv_bfloat16 *w0h, *w0l, *w1h, *w1l, *qh, *ql, *kh, *kl;
    cudaGetSymbolAddress((void**)&q1h, g_Q1h); cudaGetSymbolAddress((void**)&q1l, g_Q1l);
    cudaGetSymbolAddress((void**)&q2h, g_Q2h); cudaGetSymbolAddress((void**)&q2l, g_Q2l);
    cudaGetSymbolAddress((void**)&p1h, g_P1h); cudaGetSymbolAddress((void**)&p1l, g_P1l);
    cudaGetSymbolAddress((void**)&p2h, g_P2h); cudaGetSymbolAddress((void**)&p2l, g_P2l);
    cudaGetSymbolAddress((void**)&w0h, g_WT0h); cudaGetSymbolAddress((void**)&w0l, g_WT0l);
    cudaGetSymbolAddress((void**)&w1h, g_WT1h); cudaGetSymbolAddress((void**)&w1l, g_WT1l);
    cudaGetSymbolAddress((void**)&qh, g_qh);   cudaGetSymbolAddress((void**)&ql, g_ql);
    cudaGetSymbolAddress((void**)&kh, g_kh);   cudaGetSymbolAddress((void**)&kl, g_kl);

    cudaFuncSetAttribute(gemm_trunk, cudaFuncAttributeMaxDynamicSharedMemorySize, GEMM_SMEM);
    cudaFuncSetAttribute(sim_flash, cudaFuncAttributeMaxDynamicSharedMemorySize, GEMM_SMEM);

    static cudaStream_t s2 = nullptr;
    static cudaEvent_t evFork = nullptr, evJoin = nullptr;
    if (s2 == nullptr) {
        cudaStreamCreateWithFlags(&s2, cudaStreamNonBlocking);
        cudaEventCreateWithFlags(&evFork, cudaEventDisableTiming);
        cudaEventCreateWithFlags(&evJoin, cudaEventDisableTiming);
    }

    zero_all<<<32, 256>>>();
    cudaEventRecord(evFork, 0);
    cudaStreamWaitEvent(s2, evFork, 0);

    split_stats_b<<<dim3(D / 256, 64), 256>>>(x, q1h, q1l, B, D, 0);
    split_stats_b<<<dim3(D / 256, 64), 256, 0, s2>>>(xn, p1h, p1l, N, D, 1);

    __nv_bfloat16 *qa_h = q1h, *qa_l = q1l, *qb_h = q2h, *qb_l = q2l;
    __nv_bfloat16 *ka_h = p1h, *ka_l = p1l, *kb_h = p2h, *kb_l = p2l;

    for (int i = 0; i < 3; ++i) {
        int Din = dims[i], Dout = dims[i + 1];
        int nx = Dout / 128;
        int accum_q = (i < 2) ? 1 : 0;
        int accum_k = (i < 2) ? 1 : 2;

        // q branch (default stream)
        wprep_fused<<<dim3(Dout / 32, Din / 32), dim3(32, 8)>>>(
            Ws[i], Din, Dout, w0h, w0l, 0, i, B, gs[i], es[i]);
        __nv_bfloat16* yq_h = (i == 2) ? qh : qb_h;
        __nv_bfloat16* yq_l = (i == 2) ? ql : qb_l;
        gemm_trunk<<<dim3(nx, B / 128), 256, GEMM_SMEM>>>(
            qa_h, qa_l, w0h, w0l, bs[i], Din, Dout, accum_q, 0, i, yq_h, yq_l);

        // k branch (s2)
        wprep_fused<<<dim3(Dout / 32, Din / 32), dim3(32, 8), 0, s2>>>(
            Ws[i], Din, Dout, w1h, w1l, 1, i, N, gs[i], es[i]);
        __nv_bfloat16* yk_h = (i == 2) ? kh : kb_h;
        __nv_bfloat16* yk_l = (i == 2) ? kl : kb_l;
        gemm_trunk<<<dim3(nx, N / 128), 256, GEMM_SMEM, s2>>>(
            ka_h, ka_l, w1h, w1l, bs[i], Din, Dout, accum_k, 1, i, yk_h, yk_l);

        __nv_bfloat16* t;
        t = qa_h; qa_h = qb_h; qb_h = t;  t = qa_l; qa_l = qb_l; qb_l = t;
        t = ka_h; ka_h = kb_h; kb_h = t;  t = ka_l; ka_l = kb_l; kb_l = t;
    }

    cudaEventRecord(evJoin, s2);
    cudaStreamWaitEvent(0, evJoin, 0);

    const int NSPLIT = N / 128;
    sim_flash<<<dim3(NSPLIT, B / 128), 256, GEMM_SMEM>>>(
        qh, ql, kh, kl, y, dims[3], NSPLIT);
    combine_out<<<B / 8, 256>>>((float*)d_out, NSPLIT);
}